// round 1
// baseline (speedup 1.0000x reference)
#include <cuda_runtime.h>
#include <math.h>

#define NTOT 16384
#define AA 8
#define EE 64
#define SSZ 512
#define HYPD 256

// ---------------- scratch (device globals; no allocation allowed) ----------
__device__ float g_x[NTOT * AA * EE];    // encoder output  [N*A, 64]
__device__ float g_aq[NTOT * AA];        // attended_qs     [N, 8]
__device__ float g_h1[NTOT * HYPD];      // relu(Wh1a st)   [N, 256]
__device__ float g_hf[NTOT * HYPD];      // relu(Whfa st)   [N, 256]
__device__ float g_w1[NTOT * AA * EE];   // abs(Wh1b h1)    [N, 512]
__device__ float g_wf[NTOT * EE];        // abs(Whfb hf)    [N, 64]
__device__ float g_b1[NTOT * EE];        // Wb1 st          [N, 64]
__device__ float g_v1[NTOT * EE];        // relu(Wv1 st)    [N, 64]

enum { EPI_ID = 0, EPI_RELU = 1, EPI_ABS = 2, EPI_ENC = 3 };

// ---------------- generic SGEMM: C[M,Nout] = A[M,K] @ Bw[Nout,K]^T + bias ---
// BM=128, BN=64, BK=16, 256 threads, 8x4 micro-tile.
// Requires M%128==0, Nout%64==0, K%16==0 (true for all launches here).
template <int EPI>
__global__ void __launch_bounds__(256) sgemm_kernel(
    const float* __restrict__ A, const float* __restrict__ Bw,
    const float* __restrict__ bias, float* __restrict__ C,
    int M, int Nout, int K,
    const int* __restrict__ actions, const float* __restrict__ qvals,
    const float* __restrict__ W_act, const float* __restrict__ W_q,
    const float* __restrict__ b_act2, const float* __restrict__ b_q2)
{
    __shared__ __align__(16) float As[16][132];  // [k][m]
    __shared__ __align__(16) float Bs[16][68];   // [k][n]

    const int tid = threadIdx.x;
    const int tr = tid >> 4;   // 0..15  (rows tr*8 .. tr*8+7)
    const int tc = tid & 15;   // 0..15  (cols tc*4 .. tc*4+3)
    const int row0 = blockIdx.y * 128;
    const int col0 = blockIdx.x * 64;

    float acc[8][4];
#pragma unroll
    for (int i = 0; i < 8; i++)
#pragma unroll
        for (int j = 0; j < 4; j++) acc[i][j] = 0.f;

    const int nk = K >> 4;
    for (int kt = 0; kt < nk; ++kt) {
        // A tile: 128 rows x 16 cols = 512 float4, 2 per thread
#pragma unroll
        for (int i = 0; i < 2; i++) {
            int lin = tid + i * 256;
            int r = lin >> 2;
            int c4 = lin & 3;
            float4 v = *(const float4*)&A[(size_t)(row0 + r) * K + kt * 16 + c4 * 4];
            As[c4 * 4 + 0][r] = v.x; As[c4 * 4 + 1][r] = v.y;
            As[c4 * 4 + 2][r] = v.z; As[c4 * 4 + 3][r] = v.w;
        }
        // B tile: 64 rows x 16 cols = 256 float4, 1 per thread
        {
            int r = tid >> 2;
            int c4 = tid & 3;
            float4 v = *(const float4*)&Bw[(size_t)(col0 + r) * K + kt * 16 + c4 * 4];
            Bs[c4 * 4 + 0][r] = v.x; Bs[c4 * 4 + 1][r] = v.y;
            Bs[c4 * 4 + 2][r] = v.z; Bs[c4 * 4 + 3][r] = v.w;
        }
        __syncthreads();
#pragma unroll
        for (int kk = 0; kk < 16; kk++) {
            float4 a0 = *(const float4*)&As[kk][tr * 8];
            float4 a1 = *(const float4*)&As[kk][tr * 8 + 4];
            float4 b  = *(const float4*)&Bs[kk][tc * 4];
            float av[8] = {a0.x, a0.y, a0.z, a0.w, a1.x, a1.y, a1.z, a1.w};
            float bv[4] = {b.x, b.y, b.z, b.w};
#pragma unroll
            for (int i = 0; i < 8; i++)
#pragma unroll
                for (int j = 0; j < 4; j++) acc[i][j] += av[i] * bv[j];
        }
        __syncthreads();
    }

    const int cg = col0 + tc * 4;
    float bb[4], cextra[4], wqv[4];
#pragma unroll
    for (int j = 0; j < 4; j++) bb[j] = bias[cg + j];
    if (EPI == EPI_ENC) {
#pragma unroll
        for (int j = 0; j < 4; j++) {
            cextra[j] = b_act2[cg + j] + b_q2[cg + j];
            wqv[j] = W_q[cg + j];
        }
    }
#pragma unroll
    for (int i = 0; i < 8; i++) {
        int r = row0 + tr * 8 + i;
        float4 o;
        float v[4];
#pragma unroll
        for (int j = 0; j < 4; j++) v[j] = acc[i][j] + bb[j];
        if (EPI == EPI_ENC) {
            int act = actions[r];
            float qv = qvals[r];
#pragma unroll
            for (int j = 0; j < 4; j++)
                v[j] += cextra[j] + W_act[(cg + j) * 32 + act] + qv * wqv[j];
        } else if (EPI == EPI_RELU) {
#pragma unroll
            for (int j = 0; j < 4; j++) v[j] = fmaxf(v[j], 0.f);
        } else if (EPI == EPI_ABS) {
#pragma unroll
            for (int j = 0; j < 4; j++) v[j] = fabsf(v[j]);
        }
        o.x = v[0]; o.y = v[1]; o.z = v[2]; o.w = v[3];
        *(float4*)&C[(size_t)r * Nout + cg] = o;
    }
}

// ---------------- fused attention: qkv -> softmax -> proj -> a2q ------------
// warp-per-sample; weights staged in dynamic smem once per block.
// smem layout (floats): wq 64*196 | wo 64*68 | bqkv 192 | bo 64 | wa2q 64 |
//                       per-warp(16): xos 512, qk 1536
#define ATTN_SMEM_FLOATS (64 * 196 + 64 * 68 + 192 + 64 + 64 + 16 * 2048)

__global__ void __launch_bounds__(512) attn_kernel(
    const float* __restrict__ Wqkv, const float* __restrict__ bqkv,
    const float* __restrict__ Wo, const float* __restrict__ bo,
    const float* __restrict__ Wa2q, const float* __restrict__ ba2q)
{
    extern __shared__ float sh[];
    float* wq    = sh;                 // [k][c] transposed Wqkv, stride 196
    float* wo    = wq + 64 * 196;      // [k][c] transposed Wo, stride 68
    float* bq_sh = wo + 64 * 68;
    float* bo_sh = bq_sh + 192;
    float* wa_sh = bo_sh + 64;
    float* wbuf  = wa_sh + 64;

    const int tid = threadIdx.x;
    for (int i = tid; i < 192 * 64; i += 512) { int c = i >> 6, k = i & 63; wq[k * 196 + c] = Wqkv[i]; }
    for (int i = tid; i < 64 * 64;  i += 512) { int c = i >> 6, k = i & 63; wo[k * 68 + c] = Wo[i]; }
    if (tid < 192) bq_sh[tid] = bqkv[tid];
    if (tid < 64) { bo_sh[tid] = bo[tid]; wa_sh[tid] = Wa2q[tid]; }
    __syncthreads();

    const int warp = tid >> 5, lane = tid & 31;
    float* xos = wbuf + warp * 2048;   // x tile, later reused as o tile [8][64]
    float* qk  = xos + 512;            // qkv tile [8][192]
    const float ba2qv = ba2q[0];
    const int h = lane >> 3, a = lane & 7;

    for (int n = blockIdx.x * 16 + warp; n < NTOT; n += gridDim.x * 16) {
        const float* xg = g_x + (size_t)n * 512;
#pragma unroll
        for (int i = 0; i < 16; i++) xos[i * 32 + lane] = xg[i * 32 + lane];
        __syncwarp();

        // ---- qkv = x @ Wqkv^T + bqkv : lane owns 6 cols (cb*32+lane) x 8 rows
        float acc[6][8];
#pragma unroll
        for (int cb = 0; cb < 6; cb++)
#pragma unroll
            for (int ar = 0; ar < 8; ar++) acc[cb][ar] = 0.f;
#pragma unroll 4
        for (int k = 0; k < 64; k++) {
            float xa[8];
#pragma unroll
            for (int ar = 0; ar < 8; ar++) xa[ar] = xos[ar * 64 + k];
#pragma unroll
            for (int cb = 0; cb < 6; cb++) {
                float wv = wq[k * 196 + cb * 32 + lane];
#pragma unroll
                for (int ar = 0; ar < 8; ar++) acc[cb][ar] += xa[ar] * wv;
            }
        }
#pragma unroll
        for (int cb = 0; cb < 6; cb++) {
            float bbv = bq_sh[cb * 32 + lane];
#pragma unroll
            for (int ar = 0; ar < 8; ar++) qk[ar * 192 + cb * 32 + lane] = acc[cb][ar] + bbv;
        }
        __syncwarp();

        // ---- attention: lane = (head h, query row a)
        float q[16];
#pragma unroll
        for (int d = 0; d < 16; d++) q[d] = qk[a * 192 + h * 16 + d];
        float s[8], m = -1e30f;
#pragma unroll
        for (int b = 0; b < 8; b++) {
            float t = 0.f;
#pragma unroll
            for (int d = 0; d < 16; d++) t += q[d] * qk[b * 192 + 64 + h * 16 + d];
            s[b] = t * 0.25f;           // 1/sqrt(16)
            m = fmaxf(m, s[b]);
        }
        float sum = 0.f;
#pragma unroll
        for (int b = 0; b < 8; b++) { s[b] = __expf(s[b] - m); sum += s[b]; }
        float inv = 1.f / sum;
        float o[16];
#pragma unroll
        for (int d = 0; d < 16; d++) o[d] = 0.f;
#pragma unroll
        for (int b = 0; b < 8; b++) {
            float p = s[b] * inv;
#pragma unroll
            for (int d = 0; d < 16; d++) o[d] += p * qk[b * 192 + 128 + h * 16 + d];
        }
        __syncwarp();
#pragma unroll
        for (int d = 0; d < 16; d++) xos[a * 64 + h * 16 + d] = o[d];  // o tile
        __syncwarp();

        // ---- proj (Wo) + a2q reduce: lane owns cols {lane, lane+32}
        float pacc[2][8];
#pragma unroll
        for (int jj = 0; jj < 2; jj++)
#pragma unroll
            for (int ar = 0; ar < 8; ar++) pacc[jj][ar] = 0.f;
#pragma unroll 4
        for (int k = 0; k < 64; k++) {
            float ov[8];
#pragma unroll
            for (int ar = 0; ar < 8; ar++) ov[ar] = xos[ar * 64 + k];
#pragma unroll
            for (int jj = 0; jj < 2; jj++) {
                float wv = wo[k * 68 + jj * 32 + lane];
#pragma unroll
                for (int ar = 0; ar < 8; ar++) pacc[jj][ar] += ov[ar] * wv;
            }
        }
        float pa[8];
#pragma unroll
        for (int ar = 0; ar < 8; ar++) pa[ar] = 0.f;
#pragma unroll
        for (int jj = 0; jj < 2; jj++) {
            int c = jj * 32 + lane;
            float w2 = wa_sh[c], bbv = bo_sh[c];
#pragma unroll
            for (int ar = 0; ar < 8; ar++) pa[ar] += (pacc[jj][ar] + bbv) * w2;
        }
#pragma unroll
        for (int ar = 0; ar < 8; ar++) {
#pragma unroll
            for (int off = 16; off > 0; off >>= 1)
                pa[ar] += __shfl_xor_sync(0xffffffffu, pa[ar], off);
        }
        if (lane == 0) {
#pragma unroll
            for (int ar = 0; ar < 8; ar++) g_aq[n * 8 + ar] = pa[ar] + ba2qv;
        }
        __syncwarp();
    }
}

// ---------------- final mixing: elu(aq @ w1 + b1) . w_f + v ----------------
__global__ void __launch_bounds__(256) final_kernel(
    const float* __restrict__ Wv2, const float* __restrict__ bv2,
    float* __restrict__ out)
{
    const int warp = threadIdx.x >> 5, lane = threadIdx.x & 31;
    const int n = blockIdx.x * 8 + warp;
    if (n >= NTOT) return;

    float aqv[8];
#pragma unroll
    for (int a = 0; a < 8; a++) aqv[a] = g_aq[n * 8 + a];

    float tot = 0.f;
#pragma unroll
    for (int jj = 0; jj < 2; jj++) {
        int e = jj * 32 + lane;
        float hsum = g_b1[n * 64 + e];
#pragma unroll
        for (int a = 0; a < 8; a++) hsum += aqv[a] * g_w1[(size_t)n * 512 + a * 64 + e];
        float hid = hsum > 0.f ? hsum : expm1f(hsum);   // elu
        tot += hid * g_wf[n * 64 + e] + g_v1[n * 64 + e] * Wv2[e];
    }
#pragma unroll
    for (int off = 16; off > 0; off >>= 1) tot += __shfl_xor_sync(0xffffffffu, tot, off);
    if (lane == 0) out[n] = tot + bv2[0];
}

// ---------------- launch ----------------------------------------------------
extern "C" void kernel_launch(void* const* d_in, const int* in_sizes, int n_in,
                              void* d_out, int out_size)
{
    const float* agent_qs = (const float*)d_in[0];
    const float* states   = (const float*)d_in[1];
    const float* obs      = (const float*)d_in[2];
    const int*   actions  = (const int*)d_in[3];
    const float* W_obs = (const float*)d_in[4];  const float* b_obs = (const float*)d_in[5];
    const float* W_act = (const float*)d_in[6];  const float* b_act = (const float*)d_in[7];
    const float* W_q   = (const float*)d_in[8];  const float* b_q   = (const float*)d_in[9];
    const float* Wqkv  = (const float*)d_in[10]; const float* bqkv  = (const float*)d_in[11];
    const float* Wo    = (const float*)d_in[12]; const float* bo    = (const float*)d_in[13];
    const float* Wa2q  = (const float*)d_in[14]; const float* ba2q  = (const float*)d_in[15];
    const float* Wh1a  = (const float*)d_in[16]; const float* bh1a  = (const float*)d_in[17];
    const float* Wh1b  = (const float*)d_in[18]; const float* bh1b  = (const float*)d_in[19];
    const float* Whfa  = (const float*)d_in[20]; const float* bhfa  = (const float*)d_in[21];
    const float* Whfb  = (const float*)d_in[22]; const float* bhfb  = (const float*)d_in[23];
    const float* Wb1   = (const float*)d_in[24]; const float* bb1   = (const float*)d_in[25];
    const float* Wv1   = (const float*)d_in[26]; const float* bv1   = (const float*)d_in[27];
    const float* Wv2   = (const float*)d_in[28]; const float* bv2   = (const float*)d_in[29];
    float* out = (float*)d_out;

    void *p_x, *p_h1, *p_hf, *p_w1, *p_wf, *p_b1, *p_v1;
    cudaGetSymbolAddress(&p_x,  g_x);
    cudaGetSymbolAddress(&p_h1, g_h1);
    cudaGetSymbolAddress(&p_hf, g_hf);
    cudaGetSymbolAddress(&p_w1, g_w1);
    cudaGetSymbolAddress(&p_wf, g_wf);
    cudaGetSymbolAddress(&p_b1, g_b1);
    cudaGetSymbolAddress(&p_v1, g_v1);

    // 1) per-agent encoder: x = obs@W_obs^T + b_obs + W_act[:,act]+b_act + qs*W_q+b_q
    sgemm_kernel<EPI_ENC><<<dim3(1, 1024), 256>>>(
        obs, W_obs, b_obs, (float*)p_x, 131072, 64, 256,
        actions, agent_qs, W_act, W_q, b_act, b_q);

    // 2) fused MHA + out-proj + a2q -> attended_qs
    const int attn_smem = ATTN_SMEM_FLOATS * 4;
    cudaFuncSetAttribute(attn_kernel, cudaFuncAttributeMaxDynamicSharedMemorySize, attn_smem);
    attn_kernel<<<148, 512, attn_smem>>>(Wqkv, bqkv, Wo, bo, Wa2q, ba2q);

    // 3) hypernets on states
    sgemm_kernel<EPI_RELU><<<dim3(4, 128), 256>>>(states, Wh1a, bh1a, (float*)p_h1, NTOT, 256, 512, 0, 0, 0, 0, 0, 0);
    sgemm_kernel<EPI_RELU><<<dim3(4, 128), 256>>>(states, Whfa, bhfa, (float*)p_hf, NTOT, 256, 512, 0, 0, 0, 0, 0, 0);
    sgemm_kernel<EPI_ID  ><<<dim3(1, 128), 256>>>(states, Wb1,  bb1,  (float*)p_b1, NTOT,  64, 512, 0, 0, 0, 0, 0, 0);
    sgemm_kernel<EPI_RELU><<<dim3(1, 128), 256>>>(states, Wv1,  bv1,  (float*)p_v1, NTOT,  64, 512, 0, 0, 0, 0, 0, 0);
    sgemm_kernel<EPI_ABS ><<<dim3(8, 128), 256>>>((float*)p_h1, Wh1b, bh1b, (float*)p_w1, NTOT, 512, 256, 0, 0, 0, 0, 0, 0);
    sgemm_kernel<EPI_ABS ><<<dim3(1, 128), 256>>>((float*)p_hf, Whfb, bhfb, (float*)p_wf, NTOT,  64, 256, 0, 0, 0, 0, 0, 0);

    // 4) final mix -> y
    final_kernel<<<2048, 256>>>(Wv2, bv2, out);
}

// round 3
// speedup vs baseline: 1.7724x; 1.7724x over previous
#include <cuda_runtime.h>
#include <math.h>
#include <cstdint>

#define NTOT 16384

// ---------------- scratch (device globals; no allocation allowed) ----------
__device__ float g_x[131072 * 64];        // encoder output  [N*A, 64]
__device__ float g_qkv[131072 * 192];     // qkv             [N*A, 192]
__device__ float g_aq[NTOT * 8];          // attended_qs
__device__ float g_h1[NTOT * 256];
__device__ float g_hf[NTOT * 256];
__device__ float g_w1[NTOT * 512];
__device__ float g_wf[NTOT * 64];
__device__ float g_b1[NTOT * 64];
__device__ float g_v1[NTOT * 64];
__device__ float g_wcomb[65];             // Wa2q@Wo [64], bcomb at [64]

// ---------------- helpers ---------------------------------------------------
__device__ __forceinline__ uint32_t f2tf(float x) {   // RNA round to tf32
    uint32_t r;
    asm("cvt.rna.tf32.f32 %0, %1;" : "=r"(r) : "f"(x));
    return r;
}

// mma.sync tf32 m16n8k8: D = A*B + D (fp32 accum). Plain sm_80+ PTX -> works
// on the compute_103 (non-'a') pass; runs on Blackwell legacy-MMA path.
__device__ __forceinline__ void mma_tf32(float* c, const uint32_t* a, const uint32_t* b) {
    asm volatile(
        "mma.sync.aligned.m16n8k8.row.col.f32.tf32.tf32.f32 "
        "{%0,%1,%2,%3}, {%4,%5,%6,%7}, {%8,%9}, {%0,%1,%2,%3};\n"
        : "+f"(c[0]), "+f"(c[1]), "+f"(c[2]), "+f"(c[3])
        : "r"(a[0]), "r"(a[1]), "r"(a[2]), "r"(a[3]), "r"(b[0]), "r"(b[1]));
}

enum { EPI_ID = 0, EPI_RELU = 1, EPI_ABS = 2, EPI_ENC = 3 };

// ---------------- tf32 mma GEMM: C[M,Nout] = A[M,K] @ Bw[Nout,K]^T + bias ---
// CTA tile 128x64, 8 warps (4x2), warp tile 32x32, BK=32.
// Requires M%128==0, Nout%64==0, K%32==0 (true for all launches here).
template <int EPI>
__global__ void __launch_bounds__(256) mma_gemm(
    const float* __restrict__ A, const float* __restrict__ Bw,
    const float* __restrict__ bias, float* __restrict__ C,
    int M, int Nout, int K,
    const int* __restrict__ actions, const float* __restrict__ qvals,
    const float* __restrict__ W_act, const float* __restrict__ W_q,
    const float* __restrict__ b_act2, const float* __restrict__ b_q2)
{
    __shared__ uint32_t As[128][36];   // [m][k], pad 36 -> frag LDS conflict-free
    __shared__ uint32_t Bs[64][36];    // [n][k]
    __shared__ float bias_sh[64], cvec_sh[64], wq_sh[64];

    const int tid = threadIdx.x;
    const int wid = tid >> 5, lane = tid & 31;
    const int wm = wid >> 1, wn = wid & 1;         // warp grid 4x2
    const int g = lane >> 2, t = lane & 3;         // mma groupID / tig
    const int row0 = blockIdx.y * 128;
    const int col0 = blockIdx.x * 64;

    if (tid < 64) {
        bias_sh[tid] = bias[col0 + tid];
        if (EPI == EPI_ENC) {
            cvec_sh[tid] = b_act2[col0 + tid] + b_q2[col0 + tid];
            wq_sh[tid] = W_q[col0 + tid];
        }
    }

    float acc[2][4][4];
#pragma unroll
    for (int mi = 0; mi < 2; mi++)
#pragma unroll
        for (int ni = 0; ni < 4; ni++)
#pragma unroll
            for (int j = 0; j < 4; j++) acc[mi][ni][j] = 0.f;

    for (int c0 = 0; c0 < K; c0 += 32) {
        __syncthreads();
        // stage A: 128 rows x 32 floats = 1024 float4, 4/thread
#pragma unroll
        for (int i = 0; i < 4; i++) {
            int e = tid + i * 256;
            int r = e >> 3, q = e & 7;
            float4 v = *(const float4*)(A + (size_t)(row0 + r) * K + c0 + q * 4);
            uint4 u;
            u.x = f2tf(v.x); u.y = f2tf(v.y); u.z = f2tf(v.z); u.w = f2tf(v.w);
            *(uint4*)&As[r][q * 4] = u;
        }
        // stage B: 64 rows x 32 floats = 512 float4, 2/thread
#pragma unroll
        for (int i = 0; i < 2; i++) {
            int e = tid + i * 256;
            int r = e >> 3, q = e & 7;
            float4 v = *(const float4*)(Bw + (size_t)(col0 + r) * K + c0 + q * 4);
            uint4 u;
            u.x = f2tf(v.x); u.y = f2tf(v.y); u.z = f2tf(v.z); u.w = f2tf(v.w);
            *(uint4*)&Bs[r][q * 4] = u;
        }
        __syncthreads();

#pragma unroll
        for (int kk8 = 0; kk8 < 4; kk8++) {
            const int kk = kk8 * 8;
            uint32_t af[2][4];
#pragma unroll
            for (int mi = 0; mi < 2; mi++) {
                const int mb = wm * 32 + mi * 16 + g;
                af[mi][0] = As[mb][kk + t];
                af[mi][1] = As[mb + 8][kk + t];
                af[mi][2] = As[mb][kk + t + 4];
                af[mi][3] = As[mb + 8][kk + t + 4];
            }
            uint32_t bf[4][2];
#pragma unroll
            for (int ni = 0; ni < 4; ni++) {
                const int nb = wn * 32 + ni * 8 + g;
                bf[ni][0] = Bs[nb][kk + t];
                bf[ni][1] = Bs[nb][kk + t + 4];
            }
#pragma unroll
            for (int mi = 0; mi < 2; mi++)
#pragma unroll
                for (int ni = 0; ni < 4; ni++)
                    mma_tf32(acc[mi][ni], af[mi], bf[ni]);
        }
    }

    // ---- epilogue ----
#pragma unroll
    for (int mi = 0; mi < 2; mi++) {
#pragma unroll
        for (int half = 0; half < 2; half++) {
            const int row = row0 + wm * 32 + mi * 16 + half * 8 + g;
            int act = 0; float qv = 0.f;
            if (EPI == EPI_ENC) { act = actions[row]; qv = qvals[row]; }
#pragma unroll
            for (int ni = 0; ni < 4; ni++) {
                const int lc = wn * 32 + ni * 8 + t * 2;   // local col (0..63)
                float v0 = acc[mi][ni][half * 2 + 0] + bias_sh[lc];
                float v1 = acc[mi][ni][half * 2 + 1] + bias_sh[lc + 1];
                if (EPI == EPI_ENC) {
                    const int col = col0 + lc;
                    v0 += cvec_sh[lc] + __ldg(&W_act[(col) * 32 + act]) + qv * wq_sh[lc];
                    v1 += cvec_sh[lc + 1] + __ldg(&W_act[(col + 1) * 32 + act]) + qv * wq_sh[lc + 1];
                } else if (EPI == EPI_RELU) {
                    v0 = fmaxf(v0, 0.f); v1 = fmaxf(v1, 0.f);
                } else if (EPI == EPI_ABS) {
                    v0 = fabsf(v0); v1 = fabsf(v1);
                }
                float2 o = {v0, v1};
                *(float2*)(C + (size_t)row * Nout + col0 + lc) = o;
            }
        }
    }
}

// ---------------- wcomb = Wa2q @ Wo, bcomb = Wa2q.bo + ba2q -----------------
__global__ void wcomb_kernel(const float* __restrict__ Wa2q, const float* __restrict__ ba2q,
                             const float* __restrict__ Wo, const float* __restrict__ bo)
{
    int k = threadIdx.x;
    float s = 0.f;
    for (int c = 0; c < 64; c++) s += Wa2q[c] * Wo[c * 64 + k];
    g_wcomb[k] = s;
    if (k == 0) {
        float b = ba2q[0];
        for (int c = 0; c < 64; c++) b += Wa2q[c] * bo[c];
        g_wcomb[64] = b;
    }
}

// ---------------- attention core: softmax(QK^T)V . wcomb -> attended_qs ----
__global__ void __launch_bounds__(128) attn_core_kernel()
{
    __shared__ float sh[4][1536];
    const int tid = threadIdx.x, warp = tid >> 5, lane = tid & 31;
    const int h = lane >> 3, a = lane & 7;
    const int n = blockIdx.x * 4 + warp;
    float* t = sh[warp];
    const float4* src = (const float4*)(g_qkv + (size_t)n * 1536);
#pragma unroll
    for (int i = 0; i < 12; i++) { int e = lane + i * 32; ((float4*)t)[e] = src[e]; }
    __syncwarp();

    float q[16];
#pragma unroll
    for (int d = 0; d < 16; d++) q[d] = t[a * 192 + h * 16 + d];
    float s[8], m = -1e30f;
#pragma unroll
    for (int b = 0; b < 8; b++) {
        float acc = 0.f;
#pragma unroll
        for (int d = 0; d < 16; d++) acc += q[d] * t[b * 192 + 64 + h * 16 + d];
        s[b] = acc * 0.25f;     // 1/sqrt(16)
        m = fmaxf(m, s[b]);
    }
    float sum = 0.f;
#pragma unroll
    for (int b = 0; b < 8; b++) { s[b] = __expf(s[b] - m); sum += s[b]; }
    float inv = 1.f / sum;
    float o[16];
#pragma unroll
    for (int d = 0; d < 16; d++) o[d] = 0.f;
#pragma unroll
    for (int b = 0; b < 8; b++) {
        float p = s[b] * inv;
#pragma unroll
        for (int d = 0; d < 16; d++) o[d] += p * t[b * 192 + 128 + h * 16 + d];
    }
    float part = 0.f;
#pragma unroll
    for (int d = 0; d < 16; d++) part += o[d] * g_wcomb[h * 16 + d];
    part += __shfl_xor_sync(0xffffffffu, part, 8);
    part += __shfl_xor_sync(0xffffffffu, part, 16);
    if (h == 0) g_aq[n * 8 + a] = part + g_wcomb[64];
}

// ---------------- final mixing: elu(aq @ w1 + b1) . w_f + v ----------------
__global__ void __launch_bounds__(256) final_kernel(
    const float* __restrict__ Wv2, const float* __restrict__ bv2,
    float* __restrict__ out)
{
    const int warp = threadIdx.x >> 5, lane = threadIdx.x & 31;
    const int n = blockIdx.x * 8 + warp;
    if (n >= NTOT) return;

    float aqv[8];
#pragma unroll
    for (int a = 0; a < 8; a++) aqv[a] = g_aq[n * 8 + a];

    float tot = 0.f;
#pragma unroll
    for (int jj = 0; jj < 2; jj++) {
        int e = jj * 32 + lane;
        float hsum = g_b1[n * 64 + e];
#pragma unroll
        for (int a = 0; a < 8; a++) hsum += aqv[a] * g_w1[(size_t)n * 512 + a * 64 + e];
        float hid = hsum > 0.f ? hsum : expm1f(hsum);
        tot += hid * g_wf[n * 64 + e] + g_v1[n * 64 + e] * Wv2[e];
    }
#pragma unroll
    for (int off = 16; off > 0; off >>= 1) tot += __shfl_xor_sync(0xffffffffu, tot, off);
    if (lane == 0) out[n] = tot + bv2[0];
}

// ---------------- launch ----------------------------------------------------
extern "C" void kernel_launch(void* const* d_in, const int* in_sizes, int n_in,
                              void* d_out, int out_size)
{
    const float* agent_qs = (const float*)d_in[0];
    const float* states   = (const float*)d_in[1];
    const float* obs      = (const float*)d_in[2];
    const int*   actions  = (const int*)d_in[3];
    const float* W_obs = (const float*)d_in[4];  const float* b_obs = (const float*)d_in[5];
    const float* W_act = (const float*)d_in[6];  const float* b_act = (const float*)d_in[7];
    const float* W_q   = (const float*)d_in[8];  const float* b_q   = (const float*)d_in[9];
    const float* Wqkv  = (const float*)d_in[10]; const float* bqkv  = (const float*)d_in[11];
    const float* Wo    = (const float*)d_in[12]; const float* bo    = (const float*)d_in[13];
    const float* Wa2q  = (const float*)d_in[14]; const float* ba2q  = (const float*)d_in[15];
    const float* Wh1a  = (const float*)d_in[16]; const float* bh1a  = (const float*)d_in[17];
    const float* Wh1b  = (const float*)d_in[18]; const float* bh1b  = (const float*)d_in[19];
    const float* Whfa  = (const float*)d_in[20]; const float* bhfa  = (const float*)d_in[21];
    const float* Whfb  = (const float*)d_in[22]; const float* bhfb  = (const float*)d_in[23];
    const float* Wb1   = (const float*)d_in[24]; const float* bb1   = (const float*)d_in[25];
    const float* Wv1   = (const float*)d_in[26]; const float* bv1   = (const float*)d_in[27];
    const float* Wv2   = (const float*)d_in[28]; const float* bv2   = (const float*)d_in[29];
    float* out = (float*)d_out;

    void *p_x, *p_qkv, *p_h1, *p_hf, *p_w1, *p_wf, *p_b1, *p_v1;
    cudaGetSymbolAddress(&p_x,   g_x);
    cudaGetSymbolAddress(&p_qkv, g_qkv);
    cudaGetSymbolAddress(&p_h1,  g_h1);
    cudaGetSymbolAddress(&p_hf,  g_hf);
    cudaGetSymbolAddress(&p_w1,  g_w1);
    cudaGetSymbolAddress(&p_wf,  g_wf);
    cudaGetSymbolAddress(&p_b1,  g_b1);
    cudaGetSymbolAddress(&p_v1,  g_v1);

    // 1) encoder: x = obs@W_obs^T + b_obs + onehot(act)@W_act^T + b_act + qs*W_q + b_q
    mma_gemm<EPI_ENC><<<dim3(1, 1024), 256>>>(
        obs, W_obs, b_obs, (float*)p_x, 131072, 64, 256,
        actions, agent_qs, W_act, W_q, b_act, b_q);

    // 2) wcomb (tiny)
    wcomb_kernel<<<1, 64>>>(Wa2q, ba2q, Wo, bo);

    // 3) qkv = x @ Wqkv^T + bqkv
    mma_gemm<EPI_ID><<<dim3(3, 1024), 256>>>(
        (float*)p_x, Wqkv, bqkv, (float*)p_qkv, 131072, 192, 64, 0, 0, 0, 0, 0, 0);

    // 4) attention core -> attended_qs
    attn_core_kernel<<<4096, 128>>>();

    // 5) hypernets on states
    mma_gemm<EPI_RELU><<<dim3(4, 128), 256>>>(states, Wh1a, bh1a, (float*)p_h1, NTOT, 256, 512, 0, 0, 0, 0, 0, 0);
    mma_gemm<EPI_RELU><<<dim3(4, 128), 256>>>(states, Whfa, bhfa, (float*)p_hf, NTOT, 256, 512, 0, 0, 0, 0, 0, 0);
    mma_gemm<EPI_ID  ><<<dim3(1, 128), 256>>>(states, Wb1,  bb1,  (float*)p_b1, NTOT,  64, 512, 0, 0, 0, 0, 0, 0);
    mma_gemm<EPI_RELU><<<dim3(1, 128), 256>>>(states, Wv1,  bv1,  (float*)p_v1, NTOT,  64, 512, 0, 0, 0, 0, 0, 0);
    mma_gemm<EPI_ABS ><<<dim3(8, 128), 256>>>((float*)p_h1, Wh1b, bh1b, (float*)p_w1, NTOT, 512, 256, 0, 0, 0, 0, 0, 0);
    mma_gemm<EPI_ABS ><<<dim3(1, 128), 256>>>((float*)p_hf, Whfb, bhfb, (float*)p_wf, NTOT,  64, 256, 0, 0, 0, 0, 0, 0);

    // 6) final mix -> y
    final_kernel<<<2048, 256>>>(Wv2, bv2, out);
}

// round 4
// speedup vs baseline: 2.3364x; 1.3182x over previous
#include <cuda_runtime.h>
#include <math.h>
#include <cstdint>

#define NTOT 16384

// ---------------- scratch (device globals; no allocation allowed) ----------
__device__ float g_x[131072 * 64];        // encoder output  [N*A, 64]
__device__ float g_aq[NTOT * 8];          // attended_qs
__device__ float g_h1[NTOT * 256];
__device__ float g_hf[NTOT * 256];
__device__ float g_w1[NTOT * 512];
__device__ float g_wf[NTOT * 64];
__device__ float g_b1[NTOT * 64];
__device__ float g_v1[NTOT * 64];
__device__ float g_wcomb[65];             // Wa2q@Wo [64], bcomb at [64]

// ---------------- helpers ---------------------------------------------------
__device__ __forceinline__ uint32_t f2tf(float x) {   // RNA round to tf32
    uint32_t r;
    asm("cvt.rna.tf32.f32 %0, %1;" : "=r"(r) : "f"(x));
    return r;
}
__device__ __forceinline__ uint32_t smem_u32(const void* p) {
    uint32_t a;
    asm("{ .reg .u64 t; cvta.to.shared.u64 t, %1; cvt.u32.u64 %0, t; }" : "=r"(a) : "l"(p));
    return a;
}
__device__ __forceinline__ void cp16(uint32_t s, const void* g) {
    asm volatile("cp.async.cg.shared.global [%0], [%1], 16;" :: "r"(s), "l"(g));
}
#define CP_COMMIT asm volatile("cp.async.commit_group;" ::: "memory")
#define CP_WAIT(N) asm volatile("cp.async.wait_group %0;" :: "n"(N) : "memory")

// mma.sync tf32 m16n8k8 (sm_80+ PTX; legal on compute_103 target)
__device__ __forceinline__ void mma_tf32(float* c, const uint32_t* a, const uint32_t* b) {
    asm volatile(
        "mma.sync.aligned.m16n8k8.row.col.f32.tf32.tf32.f32 "
        "{%0,%1,%2,%3}, {%4,%5,%6,%7}, {%8,%9}, {%0,%1,%2,%3};\n"
        : "+f"(c[0]), "+f"(c[1]), "+f"(c[2]), "+f"(c[3])
        : "r"(a[0]), "r"(a[1]), "r"(a[2]), "r"(a[3]), "r"(b[0]), "r"(b[1]));
}

enum { EPI_ID = 0, EPI_RELU = 1, EPI_ABS = 2, EPI_ENC = 3 };

// ---------------- pipelined tf32 GEMM: C = A[M,K] @ Bw[Nout,K]^T + bias -----
// CTA tile 128x64, 8 warps (4x2), warp tile 32x32, BK=32, cp.async 3-stage.
// Requires M%128==0, Nout%64==0, K%32==0, K>=64.
#define AS_F 4608    // 128*36 floats per stage
#define BS_F 2304    // 64*36 floats per stage
#define GEMM_SMEM_BYTES ((3 * (AS_F + BS_F) + 192) * 4)

template <int EPI>
__global__ void __launch_bounds__(256) mma_gemm(
    const float* __restrict__ A, const float* __restrict__ Bw,
    const float* __restrict__ bias, float* __restrict__ C,
    int M, int Nout, int K,
    const int* __restrict__ actions, const float* __restrict__ qvals,
    const float* __restrict__ W_act, const float* __restrict__ W_q,
    const float* __restrict__ b_act2, const float* __restrict__ b_q2)
{
    extern __shared__ float dsm[];
    float* Asf = dsm;                       // 3 stages [128][36]
    float* Bsf = dsm + 3 * AS_F;            // 3 stages [64][36]
    float* bias_sh = dsm + 3 * (AS_F + BS_F);
    float* cvec_sh = bias_sh + 64;
    float* wq_sh   = cvec_sh + 64;

    const int tid = threadIdx.x;
    const int wid = tid >> 5, lane = tid & 31;
    const int wm = wid >> 1, wn = wid & 1;
    const int g = lane >> 2, t = lane & 3;
    const int row0 = blockIdx.y * 128;
    const int col0 = blockIdx.x * 64;

    if (tid < 64) {
        bias_sh[tid] = bias[col0 + tid];
        if (EPI == EPI_ENC) {
            cvec_sh[tid] = b_act2[col0 + tid] + b_q2[col0 + tid];
            wq_sh[tid] = W_q[col0 + tid];
        }
    }

    const uint32_t as_u = smem_u32(Asf);
    const uint32_t bs_u = smem_u32(Bsf);
    const int nk = K >> 5;

    // stage chunk c into buffer buf
    auto issue = [&](int c, int buf) {
        const float* Ab = A + (size_t)row0 * K + c * 32;
        const uint32_t ad = as_u + (uint32_t)buf * AS_F * 4;
#pragma unroll
        for (int i = 0; i < 4; i++) {
            int e = tid + i * 256;
            int r = e >> 3, q = e & 7;
            cp16(ad + (uint32_t)(r * 36 + q * 4) * 4, Ab + (size_t)r * K + q * 4);
        }
        const float* Bb = Bw + (size_t)col0 * K + c * 32;
        const uint32_t bd = bs_u + (uint32_t)buf * BS_F * 4;
#pragma unroll
        for (int i = 0; i < 2; i++) {
            int e = tid + i * 256;
            int r = e >> 3, q = e & 7;
            cp16(bd + (uint32_t)(r * 36 + q * 4) * 4, Bb + (size_t)r * K + q * 4);
        }
    };

    float acc[2][4][4];
#pragma unroll
    for (int mi = 0; mi < 2; mi++)
#pragma unroll
        for (int ni = 0; ni < 4; ni++)
#pragma unroll
            for (int j = 0; j < 4; j++) acc[mi][ni][j] = 0.f;

    issue(0, 0); CP_COMMIT;
    issue(1, 1); CP_COMMIT;

    for (int c = 0; c < nk; c++) {
        if (c + 1 < nk) { CP_WAIT(1); } else { CP_WAIT(0); }
        __syncthreads();
        if (c + 2 < nk) { issue(c + 2, (c + 2) % 3); CP_COMMIT; }

        const float* Ab = Asf + (c % 3) * AS_F;
        const float* Bb = Bsf + (c % 3) * BS_F;
#pragma unroll
        for (int kk8 = 0; kk8 < 4; kk8++) {
            const int kk = kk8 * 8;
            uint32_t af[2][4];
#pragma unroll
            for (int mi = 0; mi < 2; mi++) {
                const int mb = wm * 32 + mi * 16 + g;
                af[mi][0] = f2tf(Ab[mb * 36 + kk + t]);
                af[mi][1] = f2tf(Ab[(mb + 8) * 36 + kk + t]);
                af[mi][2] = f2tf(Ab[mb * 36 + kk + t + 4]);
                af[mi][3] = f2tf(Ab[(mb + 8) * 36 + kk + t + 4]);
            }
            uint32_t bf[4][2];
#pragma unroll
            for (int ni = 0; ni < 4; ni++) {
                const int nb = wn * 32 + ni * 8 + g;
                bf[ni][0] = f2tf(Bb[nb * 36 + kk + t]);
                bf[ni][1] = f2tf(Bb[nb * 36 + kk + t + 4]);
            }
#pragma unroll
            for (int mi = 0; mi < 2; mi++)
#pragma unroll
                for (int ni = 0; ni < 4; ni++)
                    mma_tf32(acc[mi][ni], af[mi], bf[ni]);
        }
        __syncthreads();
    }

    // ---- epilogue ----
#pragma unroll
    for (int mi = 0; mi < 2; mi++) {
#pragma unroll
        for (int half = 0; half < 2; half++) {
            const int row = row0 + wm * 32 + mi * 16 + half * 8 + g;
            int act = 0; float qv = 0.f;
            if (EPI == EPI_ENC) { act = actions[row]; qv = qvals[row]; }
#pragma unroll
            for (int ni = 0; ni < 4; ni++) {
                const int lc = wn * 32 + ni * 8 + t * 2;
                float v0 = acc[mi][ni][half * 2 + 0] + bias_sh[lc];
                float v1 = acc[mi][ni][half * 2 + 1] + bias_sh[lc + 1];
                if (EPI == EPI_ENC) {
                    const int col = col0 + lc;
                    v0 += cvec_sh[lc] + __ldg(&W_act[col * 32 + act]) + qv * wq_sh[lc];
                    v1 += cvec_sh[lc + 1] + __ldg(&W_act[(col + 1) * 32 + act]) + qv * wq_sh[lc + 1];
                } else if (EPI == EPI_RELU) {
                    v0 = fmaxf(v0, 0.f); v1 = fmaxf(v1, 0.f);
                } else if (EPI == EPI_ABS) {
                    v0 = fabsf(v0); v1 = fabsf(v1);
                }
                float2 o = {v0, v1};
                *(float2*)(C + (size_t)row * Nout + col0 + lc) = o;
            }
        }
    }
}

// ---------------- wcomb = Wa2q @ Wo, bcomb = Wa2q.bo + ba2q -----------------
__global__ void wcomb_kernel(const float* __restrict__ Wa2q, const float* __restrict__ ba2q,
                             const float* __restrict__ Wo, const float* __restrict__ bo)
{
    int k = threadIdx.x;
    float s = 0.f;
    for (int c = 0; c < 64; c++) s += Wa2q[c] * Wo[c * 64 + k];
    g_wcomb[k] = s;
    if (k == 0) {
        float b = ba2q[0];
        for (int c = 0; c < 64; c++) b += Wa2q[c] * bo[c];
        g_wcomb[64] = b;
    }
}

// ---------------- fused qkv GEMM + attention -> attended_qs -----------------
// CTA: 128 rows of g_x (=16 samples), 256 threads. qkv computed via tf32 mma
// into smem; softmax(QK^T)V . wcomb computed in-place; writes only g_aq.
#define QA_XS_F   (128 * 68)
#define QA_WS_F   (192 * 68)
#define QA_QS_F   (128 * 196)
#define QA_SMEM_BYTES ((QA_XS_F + QA_WS_F + QA_QS_F + 192 + 65) * 4)

__global__ void __launch_bounds__(256) qkv_attn_kernel(
    const float* __restrict__ Wqkv, const float* __restrict__ bqkv)
{
    extern __shared__ float sm[];
    float* xs = sm;                        // [128][68] raw fp32
    float* ws = xs + QA_XS_F;              // [192][68] raw fp32
    float* qs = ws + QA_WS_F;              // [128][196] qkv fp32
    float* bq = qs + QA_QS_F;              // 192
    float* wc = bq + 192;                  // 65

    const int tid = threadIdx.x;
    const int wid = tid >> 5, lane = tid & 31;
    const int wm = wid >> 1, wn = wid & 1;
    const int g = lane >> 2, t = lane & 3;
    const int row0 = blockIdx.x * 128;

    // ---- phase A: stage x tile + all of Wqkv ----
    const uint32_t xs_u = smem_u32(xs);
    const uint32_t ws_u = smem_u32(ws);
#pragma unroll
    for (int i = 0; i < 8; i++) {          // 2048 float4 of x
        int e = tid + i * 256;
        int r = e >> 4, q = e & 15;
        cp16(xs_u + (uint32_t)(r * 68 + q * 4) * 4, g_x + (size_t)(row0 + r) * 64 + q * 4);
    }
#pragma unroll
    for (int i = 0; i < 12; i++) {         // 3072 float4 of Wqkv
        int e = tid + i * 256;
        int r = e >> 4, q = e & 15;
        cp16(ws_u + (uint32_t)(r * 68 + q * 4) * 4, Wqkv + (size_t)r * 64 + q * 4);
    }
    if (tid < 192) bq[tid] = bqkv[tid];
    if (tid < 65) wc[tid] = g_wcomb[tid];
    CP_COMMIT; CP_WAIT(0);
    __syncthreads();

    // ---- phase B: qkv = x @ Wqkv^T, 3 column blocks of 64 ----
#pragma unroll 1
    for (int cb = 0; cb < 3; cb++) {
        float acc[2][4][4];
#pragma unroll
        for (int mi = 0; mi < 2; mi++)
#pragma unroll
            for (int ni = 0; ni < 4; ni++)
#pragma unroll
                for (int j = 0; j < 4; j++) acc[mi][ni][j] = 0.f;

#pragma unroll
        for (int kk8 = 0; kk8 < 8; kk8++) {
            const int kk = kk8 * 8;
            uint32_t af[2][4];
#pragma unroll
            for (int mi = 0; mi < 2; mi++) {
                const int mb = wm * 32 + mi * 16 + g;
                af[mi][0] = f2tf(xs[mb * 68 + kk + t]);
                af[mi][1] = f2tf(xs[(mb + 8) * 68 + kk + t]);
                af[mi][2] = f2tf(xs[mb * 68 + kk + t + 4]);
                af[mi][3] = f2tf(xs[(mb + 8) * 68 + kk + t + 4]);
            }
            uint32_t bf[4][2];
#pragma unroll
            for (int ni = 0; ni < 4; ni++) {
                const int nb = cb * 64 + wn * 32 + ni * 8 + g;
                bf[ni][0] = f2tf(ws[nb * 68 + kk + t]);
                bf[ni][1] = f2tf(ws[nb * 68 + kk + t + 4]);
            }
#pragma unroll
            for (int mi = 0; mi < 2; mi++)
#pragma unroll
                for (int ni = 0; ni < 4; ni++)
                    mma_tf32(acc[mi][ni], af[mi], bf[ni]);
        }
        // write col block to qs (+bias)
#pragma unroll
        for (int mi = 0; mi < 2; mi++)
#pragma unroll
            for (int half = 0; half < 2; half++) {
                const int row = wm * 32 + mi * 16 + half * 8 + g;
#pragma unroll
                for (int ni = 0; ni < 4; ni++) {
                    const int lc = wn * 32 + ni * 8 + t * 2;
                    qs[row * 196 + cb * 64 + lc]     = acc[mi][ni][half * 2 + 0] + bq[cb * 64 + lc];
                    qs[row * 196 + cb * 64 + lc + 1] = acc[mi][ni][half * 2 + 1] + bq[cb * 64 + lc + 1];
                }
            }
    }
    __syncthreads();

    // ---- phase C: attention per sample (2 samples per warp) ----
    const int h = lane >> 3, a = lane & 7;
#pragma unroll
    for (int s2 = 0; s2 < 2; s2++) {
        const int s = wid * 2 + s2;
        const float* base = qs + s * 8 * 196;

        float q[16];
#pragma unroll
        for (int d = 0; d < 16; d++) q[d] = base[a * 196 + h * 16 + d];
        float sc[8], m = -1e30f;
#pragma unroll
        for (int b = 0; b < 8; b++) {
            float acc = 0.f;
#pragma unroll
            for (int d = 0; d < 16; d++) acc += q[d] * base[b * 196 + 64 + h * 16 + d];
            sc[b] = acc * 0.25f;          // 1/sqrt(16)
            m = fmaxf(m, sc[b]);
        }
        float sum = 0.f;
#pragma unroll
        for (int b = 0; b < 8; b++) { sc[b] = __expf(sc[b] - m); sum += sc[b]; }
        float inv = 1.f / sum;
        float o[16];
#pragma unroll
        for (int d = 0; d < 16; d++) o[d] = 0.f;
#pragma unroll
        for (int b = 0; b < 8; b++) {
            float p = sc[b] * inv;
#pragma unroll
            for (int d = 0; d < 16; d++) o[d] += p * base[b * 196 + 128 + h * 16 + d];
        }
        float part = 0.f;
#pragma unroll
        for (int d = 0; d < 16; d++) part += o[d] * wc[h * 16 + d];
        part += __shfl_xor_sync(0xffffffffu, part, 8);
        part += __shfl_xor_sync(0xffffffffu, part, 16);
        if (h == 0) {
            const int n = blockIdx.x * 16 + s;
            g_aq[n * 8 + a] = part + wc[64];
        }
    }
}

// ---------------- final mixing: elu(aq @ w1 + b1) . w_f + v ----------------
__global__ void __launch_bounds__(256) final_kernel(
    const float* __restrict__ Wv2, const float* __restrict__ bv2,
    float* __restrict__ out)
{
    const int warp = threadIdx.x >> 5, lane = threadIdx.x & 31;
    const int n = blockIdx.x * 8 + warp;
    if (n >= NTOT) return;

    float aqv[8];
#pragma unroll
    for (int a = 0; a < 8; a++) aqv[a] = g_aq[n * 8 + a];

    float tot = 0.f;
#pragma unroll
    for (int jj = 0; jj < 2; jj++) {
        int e = jj * 32 + lane;
        float hsum = g_b1[n * 64 + e];
#pragma unroll
        for (int a = 0; a < 8; a++) hsum += aqv[a] * g_w1[(size_t)n * 512 + a * 64 + e];
        float hid = hsum > 0.f ? hsum : expm1f(hsum);
        tot += hid * g_wf[n * 64 + e] + g_v1[n * 64 + e] * Wv2[e];
    }
#pragma unroll
    for (int off = 16; off > 0; off >>= 1) tot += __shfl_xor_sync(0xffffffffu, tot, off);
    if (lane == 0) out[n] = tot + bv2[0];
}

// ---------------- launch ----------------------------------------------------
extern "C" void kernel_launch(void* const* d_in, const int* in_sizes, int n_in,
                              void* d_out, int out_size)
{
    const float* agent_qs = (const float*)d_in[0];
    const float* states   = (const float*)d_in[1];
    const float* obs      = (const float*)d_in[2];
    const int*   actions  = (const int*)d_in[3];
    const float* W_obs = (const float*)d_in[4];  const float* b_obs = (const float*)d_in[5];
    const float* W_act = (const float*)d_in[6];  const float* b_act = (const float*)d_in[7];
    const float* W_q   = (const float*)d_in[8];  const float* b_q   = (const float*)d_in[9];
    const float* Wqkv  = (const float*)d_in[10]; const float* bqkv  = (const float*)d_in[11];
    const float* Wo    = (const float*)d_in[12]; const float* bo    = (const float*)d_in[13];
    const float* Wa2q  = (const float*)d_in[14]; const float* ba2q  = (const float*)d_in[15];
    const float* Wh1a  = (const float*)d_in[16]; const float* bh1a  = (const float*)d_in[17];
    const float* Wh1b  = (const float*)d_in[18]; const float* bh1b  = (const float*)d_in[19];
    const float* Whfa  = (const float*)d_in[20]; const float* bhfa  = (const float*)d_in[21];
    const float* Whfb  = (const float*)d_in[22]; const float* bhfb  = (const float*)d_in[23];
    const float* Wb1   = (const float*)d_in[24]; const float* bb1   = (const float*)d_in[25];
    const float* Wv1   = (const float*)d_in[26]; const float* bv1   = (const float*)d_in[27];
    const float* Wv2   = (const float*)d_in[28]; const float* bv2   = (const float*)d_in[29];
    float* out = (float*)d_out;

    void *p_x, *p_h1, *p_hf, *p_w1, *p_wf, *p_b1, *p_v1;
    cudaGetSymbolAddress(&p_x,   g_x);
    cudaGetSymbolAddress(&p_h1,  g_h1);
    cudaGetSymbolAddress(&p_hf,  g_hf);
    cudaGetSymbolAddress(&p_w1,  g_w1);
    cudaGetSymbolAddress(&p_wf,  g_wf);
    cudaGetSymbolAddress(&p_b1,  g_b1);
    cudaGetSymbolAddress(&p_v1,  g_v1);

    cudaFuncSetAttribute(mma_gemm<EPI_ID>,   cudaFuncAttributeMaxDynamicSharedMemorySize, GEMM_SMEM_BYTES);
    cudaFuncSetAttribute(mma_gemm<EPI_RELU>, cudaFuncAttributeMaxDynamicSharedMemorySize, GEMM_SMEM_BYTES);
    cudaFuncSetAttribute(mma_gemm<EPI_ABS>,  cudaFuncAttributeMaxDynamicSharedMemorySize, GEMM_SMEM_BYTES);
    cudaFuncSetAttribute(mma_gemm<EPI_ENC>,  cudaFuncAttributeMaxDynamicSharedMemorySize, GEMM_SMEM_BYTES);
    cudaFuncSetAttribute(qkv_attn_kernel,    cudaFuncAttributeMaxDynamicSharedMemorySize, QA_SMEM_BYTES);

    // 1) encoder: x = obs@W_obs^T + b_obs + onehot(act)@W_act^T + b_act + qs*W_q + b_q
    mma_gemm<EPI_ENC><<<dim3(1, 1024), 256, GEMM_SMEM_BYTES>>>(
        obs, W_obs, b_obs, (float*)p_x, 131072, 64, 256,
        actions, agent_qs, W_act, W_q, b_act, b_q);

    // 2) wcomb (tiny)
    wcomb_kernel<<<1, 64>>>(Wa2q, ba2q, Wo, bo);

    // 3) fused qkv + attention -> attended_qs
    qkv_attn_kernel<<<1024, 256, QA_SMEM_BYTES>>>(Wqkv, bqkv);

    // 4) hypernets on states
    mma_gemm<EPI_RELU><<<dim3(4, 128), 256, GEMM_SMEM_BYTES>>>(states, Wh1a, bh1a, (float*)p_h1, NTOT, 256, 512, 0, 0, 0, 0, 0, 0);
    mma_gemm<EPI_RELU><<<dim3(4, 128), 256, GEMM_SMEM_BYTES>>>(states, Whfa, bhfa, (float*)p_hf, NTOT, 256, 512, 0, 0, 0, 0, 0, 0);
    mma_gemm<EPI_ID  ><<<dim3(1, 128), 256, GEMM_SMEM_BYTES>>>(states, Wb1,  bb1,  (float*)p_b1, NTOT,  64, 512, 0, 0, 0, 0, 0, 0);
    mma_gemm<EPI_RELU><<<dim3(1, 128), 256, GEMM_SMEM_BYTES>>>(states, Wv1,  bv1,  (float*)p_v1, NTOT,  64, 512, 0, 0, 0, 0, 0, 0);
    mma_gemm<EPI_ABS ><<<dim3(8, 128), 256, GEMM_SMEM_BYTES>>>((float*)p_h1, Wh1b, bh1b, (float*)p_w1, NTOT, 512, 256, 0, 0, 0, 0, 0, 0);
    mma_gemm<EPI_ABS ><<<dim3(1, 128), 256, GEMM_SMEM_BYTES>>>((float*)p_hf, Whfb, bhfb, (float*)p_wf, NTOT,  64, 256, 0, 0, 0, 0, 0, 0);

    // 5) final mix -> y
    final_kernel<<<2048, 256>>>(Wv2, bv2, out);
}

// round 6
// speedup vs baseline: 2.5626x; 1.0968x over previous
#include <cuda_runtime.h>
#include <math.h>
#include <cstdint>

#define NTOT 16384
#define AS_F 4608          // 128*36 floats per stage
#define BS_F 2304          // 64*36 floats per stage

// ---------------- scratch (device globals; no allocation allowed) ----------
__device__ __align__(16) float g_x[131072 * 64];    // encoder out (tf32-rounded)
__device__ __align__(16) float g_stf[NTOT * 512];   // tf32-rounded states
__device__ __align__(16) float g_wtf[503808];       // tf32-rounded weights pool
__device__ __align__(16) float g_aq[NTOT * 8];
__device__ __align__(16) float g_h1[NTOT * 256];
__device__ __align__(16) float g_hf[NTOT * 256];
__device__ __align__(16) float g_w1[NTOT * 512];
__device__ __align__(16) float g_wf[NTOT * 64];
__device__ __align__(16) float g_b1[NTOT * 64];
__device__ __align__(16) float g_v1[NTOT * 64];
__device__ float g_wcomb[65];

// offsets (floats) in g_wtf
#define OFF_WOBS 0
#define OFF_WQKV 16384
#define OFF_WH1A 28672
#define OFF_WHFA 159744
#define OFF_WH1B 290816
#define OFF_WHFB 421888
#define OFF_WB1  438272
#define OFF_WV1  471040
#define WTF_TOTAL 503808

// ---------------- helpers ---------------------------------------------------
__device__ __forceinline__ uint32_t f2tf(float x) {   // RNA round to tf32
    uint32_t r;
    asm("cvt.rna.tf32.f32 %0, %1;" : "=r"(r) : "f"(x));
    return r;
}
__device__ __forceinline__ uint32_t smem_u32(const void* p) {
    uint32_t a;
    asm("{ .reg .u64 t; cvta.to.shared.u64 t, %1; cvt.u32.u64 %0, t; }" : "=r"(a) : "l"(p));
    return a;
}
__device__ __forceinline__ void cp16(uint32_t s, const void* g) {
    asm volatile("cp.async.cg.shared.global [%0], [%1], 16;" :: "r"(s), "l"(g));
}
#define CP_COMMIT asm volatile("cp.async.commit_group;" ::: "memory")
#define CP_WAIT(N) asm volatile("cp.async.wait_group %0;" :: "n"(N) : "memory")

__device__ __forceinline__ void mma_tf32(float* c, const uint32_t* a, const uint32_t* b) {
    asm volatile(
        "mma.sync.aligned.m16n8k8.row.col.f32.tf32.tf32.f32 "
        "{%0,%1,%2,%3}, {%4,%5,%6,%7}, {%8,%9}, {%0,%1,%2,%3};\n"
        : "+f"(c[0]), "+f"(c[1]), "+f"(c[2]), "+f"(c[3])
        : "r"(a[0]), "r"(a[1]), "r"(a[2]), "r"(a[3]), "r"(b[0]), "r"(b[1]));
}

// ---- compute one 128x64x32 chunk from natural [r][36] tiles ----------------
// k-slot permutation: logical k = 8t + 2*kk8 + half  (valid: applied to A & B)
template <int CVTA>
__device__ __forceinline__ void compute_chunk(
    const float* __restrict__ Ab, const float* __restrict__ Bb,
    float acc[2][4][4], int wm, int wn, int g, int t)
{
    float a8[4][8], b8[4][8];
#pragma unroll
    for (int i = 0; i < 4; i++) {
        const float* pr = Ab + (wm * 32 + i * 8 + g) * 36 + t * 8;
        *(float4*)&a8[i][0] = *(const float4*)pr;
        *(float4*)&a8[i][4] = *(const float4*)(pr + 4);
    }
#pragma unroll
    for (int i = 0; i < 4; i++) {
        const float* pr = Bb + (wn * 32 + i * 8 + g) * 36 + t * 8;
        *(float4*)&b8[i][0] = *(const float4*)pr;
        *(float4*)&b8[i][4] = *(const float4*)(pr + 4);
    }
#pragma unroll
    for (int k8 = 0; k8 < 4; k8++) {
        uint32_t af[2][4], bf[4][2];
#pragma unroll
        for (int mi = 0; mi < 2; mi++) {
            if (CVTA) {
                af[mi][0] = f2tf(a8[2 * mi][2 * k8]);
                af[mi][1] = f2tf(a8[2 * mi + 1][2 * k8]);
                af[mi][2] = f2tf(a8[2 * mi][2 * k8 + 1]);
                af[mi][3] = f2tf(a8[2 * mi + 1][2 * k8 + 1]);
            } else {
                af[mi][0] = __float_as_uint(a8[2 * mi][2 * k8]);
                af[mi][1] = __float_as_uint(a8[2 * mi + 1][2 * k8]);
                af[mi][2] = __float_as_uint(a8[2 * mi][2 * k8 + 1]);
                af[mi][3] = __float_as_uint(a8[2 * mi + 1][2 * k8 + 1]);
            }
        }
#pragma unroll
        for (int ni = 0; ni < 4; ni++) {
            bf[ni][0] = __float_as_uint(b8[ni][2 * k8]);
            bf[ni][1] = __float_as_uint(b8[ni][2 * k8 + 1]);
        }
#pragma unroll
        for (int mi = 0; mi < 2; mi++)
#pragma unroll
            for (int ni = 0; ni < 4; ni++)
                mma_tf32(acc[mi][ni], af[mi], bf[ni]);
    }
}

__device__ __forceinline__ void issue_stage(
    const float* __restrict__ A, const float* __restrict__ B, int K,
    int row0, int col0, uint32_t as_u, uint32_t bs_u, int c, int buf, int tid)
{
    const float* Ab = A + (size_t)row0 * K + c * 32;
    const uint32_t ad = as_u + (uint32_t)buf * AS_F * 4;
#pragma unroll
    for (int i = 0; i < 4; i++) {
        int e = tid + i * 256, r = e >> 3, q = e & 7;
        cp16(ad + (uint32_t)(r * 36 + q * 4) * 4, Ab + (size_t)r * K + q * 4);
    }
    const float* Bb = B + (size_t)col0 * K + c * 32;
    const uint32_t bd = bs_u + (uint32_t)buf * BS_F * 4;
#pragma unroll
    for (int i = 0; i < 2; i++) {
        int e = tid + i * 256, r = e >> 3, q = e & 7;
        cp16(bd + (uint32_t)(r * 36 + q * 4) * 4, Bb + (size_t)r * K + q * 4);
    }
}

template <int CVTA>
__device__ __forceinline__ void gemm_main(
    const float* __restrict__ A, const float* __restrict__ B, int K,
    int row0, int col0, float* Asf, float* Bsf,
    float acc[2][4][4], int tid, int wm, int wn, int g, int t)
{
    const uint32_t as_u = smem_u32(Asf), bs_u = smem_u32(Bsf);
    const int nk = K >> 5;
    issue_stage(A, B, K, row0, col0, as_u, bs_u, 0, 0, tid); CP_COMMIT;
    issue_stage(A, B, K, row0, col0, as_u, bs_u, 1, 1, tid); CP_COMMIT;
    for (int c = 0; c < nk; c++) {
        if (c + 1 < nk) { CP_WAIT(1); } else { CP_WAIT(0); }
        __syncthreads();
        if (c + 2 < nk) { issue_stage(A, B, K, row0, col0, as_u, bs_u, c + 2, (c + 2) % 3, tid); CP_COMMIT; }
        compute_chunk<CVTA>(Asf + (c % 3) * AS_F, Bsf + (c % 3) * BS_F, acc, wm, wn, g, t);
        __syncthreads();
    }
}

// ---------------- pre-conversion kernels ------------------------------------
__global__ void __launch_bounds__(256) cvt_states_kernel(
    const float* __restrict__ s, float* __restrict__ d)
{
    size_t i = (size_t)(blockIdx.x * 256 + threadIdx.x) * 4;
    float4 v = *(const float4*)(s + i);
    uint4 u = { f2tf(v.x), f2tf(v.y), f2tf(v.z), f2tf(v.w) };
    *(uint4*)(d + i) = u;
}

struct WSeg { const float* src; int off; int cnt; };
struct WSegs { WSeg v[8]; };

__global__ void __launch_bounds__(256) cvt_weights_kernel(WSegs segs, float* __restrict__ dst)
{
    int i4 = (blockIdx.x * 256 + threadIdx.x) * 4;
#pragma unroll
    for (int s = 0; s < 8; s++) {
        int off = segs.v[s].off, cnt = segs.v[s].cnt;
        if (i4 >= off && i4 < off + cnt) {
            float4 v = *(const float4*)(segs.v[s].src + (i4 - off));
            uint4 u = { f2tf(v.x), f2tf(v.y), f2tf(v.z), f2tf(v.w) };
            *(uint4*)(dst + i4) = u;
        }
    }
}

// ---------------- encoder GEMM (obs raw -> x, tf32-rounded out) -------------
#define ENC_SMEM_BYTES ((3 * (AS_F + BS_F) + 192) * 4)

__global__ void __launch_bounds__(256, 2) enc_gemm(
    const float* __restrict__ obs, const float* __restrict__ Wobs_tf,
    const float* __restrict__ b_obs, float* __restrict__ Cx,
    const int* __restrict__ actions, const float* __restrict__ qvals,
    const float* __restrict__ W_act, const float* __restrict__ W_q,
    const float* __restrict__ b_act, const float* __restrict__ b_q)
{
    extern __shared__ float dsm[];
    float* Asf = dsm;
    float* Bsf = dsm + 3 * AS_F;
    float* bias_sh = dsm + 3 * (AS_F + BS_F);
    float* cvec_sh = bias_sh + 64;
    float* wq_sh   = cvec_sh + 64;

    const int tid = threadIdx.x;
    const int wid = tid >> 5, lane = tid & 31;
    const int wm = wid >> 1, wn = wid & 1;
    const int g = lane >> 2, t = lane & 3;
    const int row0 = blockIdx.y * 128;

    if (tid < 64) {
        bias_sh[tid] = b_obs[tid];
        cvec_sh[tid] = b_act[tid] + b_q[tid];
        wq_sh[tid] = W_q[tid];
    }

    float acc[2][4][4];
#pragma unroll
    for (int mi = 0; mi < 2; mi++)
#pragma unroll
        for (int ni = 0; ni < 4; ni++)
#pragma unroll
            for (int j = 0; j < 4; j++) acc[mi][ni][j] = 0.f;

    gemm_main<1>(obs, Wobs_tf, 256, row0, 0, Asf, Bsf, acc, tid, wm, wn, g, t);

#pragma unroll
    for (int mi = 0; mi < 2; mi++)
#pragma unroll
        for (int half = 0; half < 2; half++) {
            const int row = row0 + wm * 32 + mi * 16 + half * 8 + g;
            const int act = actions[row];
            const float qv = qvals[row];
            float* dst = Cx + (size_t)row * 64;
#pragma unroll
            for (int ni = 0; ni < 4; ni++) {
                const int lc = wn * 32 + ni * 8 + t * 2;
                float v0 = acc[mi][ni][half * 2 + 0] + bias_sh[lc]
                         + cvec_sh[lc] + __ldg(&W_act[lc * 32 + act]) + qv * wq_sh[lc];
                float v1 = acc[mi][ni][half * 2 + 1] + bias_sh[lc + 1]
                         + cvec_sh[lc + 1] + __ldg(&W_act[(lc + 1) * 32 + act]) + qv * wq_sh[lc + 1];
                float2 o = { __uint_as_float(f2tf(v0)), __uint_as_float(f2tf(v1)) };
                *(float2*)(dst + lc) = o;
            }
        }
}

// ---------------- packed GEMM (multiple ops per launch) ---------------------
struct GOp {
    const float* A; const float* B; const float* bias; float* C;
    int K; int Nout; int col0; int epi; int round; int pad;
};
struct GOps { GOp v[10]; };
#define G_SMEM_BYTES ((3 * (AS_F + BS_F) + 64) * 4)

__global__ void __launch_bounds__(256, 2) packed_gemm(GOps ops)
{
    extern __shared__ float dsm[];
    float* Asf = dsm;
    float* Bsf = dsm + 3 * AS_F;
    float* bias_sh = dsm + 3 * (AS_F + BS_F);

    const GOp op = ops.v[blockIdx.x];
    const int tid = threadIdx.x;
    const int wid = tid >> 5, lane = tid & 31;
    const int wm = wid >> 1, wn = wid & 1;
    const int g = lane >> 2, t = lane & 3;
    const int row0 = blockIdx.y * 128;
    const int col0 = op.col0;

    if (tid < 64) bias_sh[tid] = op.bias[col0 + tid];

    float acc[2][4][4];
#pragma unroll
    for (int mi = 0; mi < 2; mi++)
#pragma unroll
        for (int ni = 0; ni < 4; ni++)
#pragma unroll
            for (int j = 0; j < 4; j++) acc[mi][ni][j] = 0.f;

    gemm_main<0>(op.A, op.B, op.K, row0, col0, Asf, Bsf, acc, tid, wm, wn, g, t);

    const int epi = op.epi, rnd = op.round, Nout = op.Nout;
#pragma unroll
    for (int mi = 0; mi < 2; mi++)
#pragma unroll
        for (int half = 0; half < 2; half++) {
            const int row = row0 + wm * 32 + mi * 16 + half * 8 + g;
            float* dst = op.C + (size_t)row * Nout + col0;
#pragma unroll
            for (int ni = 0; ni < 4; ni++) {
                const int lc = wn * 32 + ni * 8 + t * 2;
                float v0 = acc[mi][ni][half * 2 + 0] + bias_sh[lc];
                float v1 = acc[mi][ni][half * 2 + 1] + bias_sh[lc + 1];
                if (epi == 1) { v0 = fmaxf(v0, 0.f); v1 = fmaxf(v1, 0.f); }
                else if (epi == 2) { v0 = fabsf(v0); v1 = fabsf(v1); }
                if (rnd) { v0 = __uint_as_float(f2tf(v0)); v1 = __uint_as_float(f2tf(v1)); }
                float2 o = { v0, v1 };
                *(float2*)(dst + lc) = o;
            }
        }
}

// ---------------- wcomb = Wa2q @ Wo, bcomb = Wa2q.bo + ba2q -----------------
__global__ void wcomb_kernel(const float* __restrict__ Wa2q, const float* __restrict__ ba2q,
                             const float* __restrict__ Wo, const float* __restrict__ bo)
{
    int k = threadIdx.x;
    float s = 0.f;
    for (int c = 0; c < 64; c++) s += Wa2q[c] * Wo[c * 64 + k];
    g_wcomb[k] = s;
    if (k == 0) {
        float b = ba2q[0];
        for (int c = 0; c < 64; c++) b += Wa2q[c] * bo[c];
        g_wcomb[64] = b;
    }
}

// ---------------- fused qkv GEMM + attention -> attended_qs -----------------
// xs/ws stored as two 32-k chunk planes of [r][36] (same scheme as gemm).
#define QA_XS_F (2 * 128 * 36)
#define QA_WS_F (2 * 192 * 36)
#define QA_QS_F (128 * 196)
#define QA_SMEM_BYTES ((QA_XS_F + QA_WS_F + QA_QS_F + 192 + 65) * 4)

__global__ void __launch_bounds__(256) qkv_attn_kernel(
    const float* __restrict__ Wqkv_tf, const float* __restrict__ bqkv)
{
    extern __shared__ float sm[];
    float* xs = sm;                        // [2][128][36]
    float* ws = xs + QA_XS_F;              // [2][192][36]
    float* qs = ws + QA_WS_F;              // [128][196]
    float* bq = qs + QA_QS_F;              // 192
    float* wc = bq + 192;                  // 65

    const int tid = threadIdx.x;
    const int wid = tid >> 5, lane = tid & 31;
    const int wm = wid >> 1, wn = wid & 1;
    const int g = lane >> 2, t = lane & 3;
    const int row0 = blockIdx.x * 128;

    const uint32_t xs_u = smem_u32(xs);
    const uint32_t ws_u = smem_u32(ws);
#pragma unroll
    for (int i = 0; i < 8; i++) {          // x tile: 2048 float4
        int e = tid + i * 256;
        int r = e >> 4, q = e & 15;
        cp16(xs_u + (uint32_t)((q >> 3) * (128 * 36) + r * 36 + (q & 7) * 4) * 4,
             g_x + (size_t)(row0 + r) * 64 + q * 4);
    }
#pragma unroll
    for (int i = 0; i < 12; i++) {         // Wqkv: 3072 float4
        int e = tid + i * 256;
        int n = e >> 4, q = e & 15;
        cp16(ws_u + (uint32_t)((q >> 3) * (192 * 36) + n * 36 + (q & 7) * 4) * 4,
             Wqkv_tf + (size_t)n * 64 + q * 4);
    }
    if (tid < 192) bq[tid] = bqkv[tid];
    if (tid < 65) wc[tid] = g_wcomb[tid];
    CP_COMMIT; CP_WAIT(0);
    __syncthreads();

    // ---- phase B: qkv = x @ Wqkv^T (3 col blocks of 64) ----
#pragma unroll 1
    for (int cb = 0; cb < 3; cb++) {
        float acc[2][4][4];
#pragma unroll
        for (int mi = 0; mi < 2; mi++)
#pragma unroll
            for (int ni = 0; ni < 4; ni++)
#pragma unroll
                for (int j = 0; j < 4; j++) acc[mi][ni][j] = 0.f;

#pragma unroll
        for (int c = 0; c < 2; c++)
            compute_chunk<0>(xs + c * (128 * 36),
                             ws + c * (192 * 36) + (cb * 64) * 36,
                             acc, wm, wn, g, t);

#pragma unroll
        for (int mi = 0; mi < 2; mi++)
#pragma unroll
            for (int half = 0; half < 2; half++) {
                const int row = wm * 32 + mi * 16 + half * 8 + g;
#pragma unroll
                for (int ni = 0; ni < 4; ni++) {
                    const int lc = wn * 32 + ni * 8 + t * 2;
                    qs[row * 196 + cb * 64 + lc]     = acc[mi][ni][half * 2 + 0] + bq[cb * 64 + lc];
                    qs[row * 196 + cb * 64 + lc + 1] = acc[mi][ni][half * 2 + 1] + bq[cb * 64 + lc + 1];
                }
            }
    }
    __syncthreads();

    // ---- phase C: attention per sample (2 samples per warp) ----
    const int h = lane >> 3, a = lane & 7;
#pragma unroll
    for (int s2 = 0; s2 < 2; s2++) {
        const int s = wid * 2 + s2;
        const float* base = qs + s * 8 * 196;

        float q[16];
#pragma unroll
        for (int d = 0; d < 16; d++) q[d] = base[a * 196 + h * 16 + d];
        float sc[8], m = -1e30f;
#pragma unroll
        for (int b = 0; b < 8; b++) {
            float acc = 0.f;
#pragma unroll
            for (int d = 0; d < 16; d++) acc += q[d] * base[b * 196 + 64 + h * 16 + d];
            sc[b] = acc * 0.25f;          // 1/sqrt(16)
            m = fmaxf(m, sc[b]);
        }
        float sum = 0.f;
#pragma unroll
        for (int b = 0; b < 8; b++) { sc[b] = __expf(sc[b] - m); sum += sc[b]; }
        float inv = 1.f / sum;
        float o[16];
#pragma unroll
        for (int d = 0; d < 16; d++) o[d] = 0.f;
#pragma unroll
        for (int b = 0; b < 8; b++) {
            float p = sc[b] * inv;
#pragma unroll
            for (int d = 0; d < 16; d++) o[d] += p * base[b * 196 + 128 + h * 16 + d];
        }
        float part = 0.f;
#pragma unroll
        for (int d = 0; d < 16; d++) part += o[d] * wc[h * 16 + d];
        part += __shfl_xor_sync(0xffffffffu, part, 8);
        part += __shfl_xor_sync(0xffffffffu, part, 16);
        if (h == 0) {
            const int n = blockIdx.x * 16 + s;
            g_aq[n * 8 + a] = part + wc[64];
        }
    }
}

// ---------------- final mixing: elu(aq @ w1 + b1) . w_f + v ----------------
__global__ void __launch_bounds__(256) final_kernel(
    const float* __restrict__ Wv2, const float* __restrict__ bv2,
    float* __restrict__ out)
{
    const int warp = threadIdx.x >> 5, lane = threadIdx.x & 31;
    const int n = blockIdx.x * 8 + warp;
    if (n >= NTOT) return;

    float aqv[8];
#pragma unroll
    for (int a = 0; a < 8; a++) aqv[a] = g_aq[n * 8 + a];

    float tot = 0.f;
#pragma unroll
    for (int jj = 0; jj < 2; jj++) {
        int e = jj * 32 + lane;
        float hsum = g_b1[n * 64 + e];
#pragma unroll
        for (int a = 0; a < 8; a++) hsum += aqv[a] * g_w1[(size_t)n * 512 + a * 64 + e];
        float hid = hsum > 0.f ? hsum : expm1f(hsum);
        tot += hid * g_wf[n * 64 + e] + g_v1[n * 64 + e] * Wv2[e];
    }
#pragma unroll
    for (int off = 16; off > 0; off >>= 1) tot += __shfl_xor_sync(0xffffffffu, tot, off);
    if (lane == 0) out[n] = tot + bv2[0];
}

// ---------------- launch ----------------------------------------------------
extern "C" void kernel_launch(void* const* d_in, const int* in_sizes, int n_in,
                              void* d_out, int out_size)
{
    const float* agent_qs = (const float*)d_in[0];
    const float* states   = (const float*)d_in[1];
    const float* obs      = (const float*)d_in[2];
    const int*   actions  = (const int*)d_in[3];
    const float* W_obs = (const float*)d_in[4];  const float* b_obs = (const float*)d_in[5];
    const float* W_act = (const float*)d_in[6];  const float* b_act = (const float*)d_in[7];
    const float* W_q   = (const float*)d_in[8];  const float* b_q   = (const float*)d_in[9];
    const float* Wqkv  = (const float*)d_in[10]; const float* bqkv  = (const float*)d_in[11];
    const float* Wo    = (const float*)d_in[12]; const float* bo    = (const float*)d_in[13];
    const float* Wa2q  = (const float*)d_in[14]; const float* ba2q  = (const float*)d_in[15];
    const float* Wh1a  = (const float*)d_in[16]; const float* bh1a  = (const float*)d_in[17];
    const float* Wh1b  = (const float*)d_in[18]; const float* bh1b  = (const float*)d_in[19];
    const float* Whfa  = (const float*)d_in[20]; const float* bhfa  = (const float*)d_in[21];
    const float* Whfb  = (const float*)d_in[22]; const float* bhfb  = (const float*)d_in[23];
    const float* Wb1   = (const float*)d_in[24]; const float* bb1   = (const float*)d_in[25];
    const float* Wv1   = (const float*)d_in[26]; const float* bv1   = (const float*)d_in[27];
    const float* Wv2   = (const float*)d_in[28]; const float* bv2   = (const float*)d_in[29];
    float* out = (float*)d_out;

    void *p_x, *p_stf, *p_wtf, *p_h1, *p_hf, *p_w1, *p_wf, *p_b1, *p_v1;
    cudaGetSymbolAddress(&p_x,   g_x);
    cudaGetSymbolAddress(&p_stf, g_stf);
    cudaGetSymbolAddress(&p_wtf, g_wtf);
    cudaGetSymbolAddress(&p_h1,  g_h1);
    cudaGetSymbolAddress(&p_hf,  g_hf);
    cudaGetSymbolAddress(&p_w1,  g_w1);
    cudaGetSymbolAddress(&p_wf,  g_wf);
    cudaGetSymbolAddress(&p_b1,  g_b1);
    cudaGetSymbolAddress(&p_v1,  g_v1);
    float* wtf = (float*)p_wtf;

    cudaFuncSetAttribute(enc_gemm,        cudaFuncAttributeMaxDynamicSharedMemorySize, ENC_SMEM_BYTES);
    cudaFuncSetAttribute(packed_gemm,     cudaFuncAttributeMaxDynamicSharedMemorySize, G_SMEM_BYTES);
    cudaFuncSetAttribute(qkv_attn_kernel, cudaFuncAttributeMaxDynamicSharedMemorySize, QA_SMEM_BYTES);

    // 0) pre-convert states + weights to tf32-rounded fp32
    cvt_states_kernel<<<8192, 256>>>(states, (float*)p_stf);
    WSegs segs;
    segs.v[0] = { W_obs, OFF_WOBS, 16384 };
    segs.v[1] = { Wqkv,  OFF_WQKV, 12288 };
    segs.v[2] = { Wh1a,  OFF_WH1A, 131072 };
    segs.v[3] = { Whfa,  OFF_WHFA, 131072 };
    segs.v[4] = { Wh1b,  OFF_WH1B, 131072 };
    segs.v[5] = { Whfb,  OFF_WHFB, 16384 };
    segs.v[6] = { Wb1,   OFF_WB1,  32768 };
    segs.v[7] = { Wv1,   OFF_WV1,  32768 };
    cvt_weights_kernel<<<WTF_TOTAL / 1024, 256>>>(segs, wtf);

    // 1) encoder -> g_x (tf32-rounded)
    enc_gemm<<<dim3(1, 1024), 256, ENC_SMEM_BYTES>>>(
        obs, wtf + OFF_WOBS, b_obs, (float*)p_x,
        actions, agent_qs, W_act, W_q, b_act, b_q);

    // 2) wcomb (tiny)
    wcomb_kernel<<<1, 64>>>(Wa2q, ba2q, Wo, bo);

    // 3) fused qkv + attention -> attended_qs
    qkv_attn_kernel<<<1024, 256, QA_SMEM_BYTES>>>(wtf + OFF_WQKV, bqkv);

    // 4) hypernets on states (one packed launch: h1 x4, hf x4, b1, v1)
    GOps opsA = {};
    for (int i = 0; i < 4; i++)
        opsA.v[i]     = { (float*)p_stf, wtf + OFF_WH1A, bh1a, (float*)p_h1, 512, 256, i * 64, 1, 1, 0 };
    for (int i = 0; i < 4; i++)
        opsA.v[4 + i] = { (float*)p_stf, wtf + OFF_WHFA, bhfa, (float*)p_hf, 512, 256, i * 64, 1, 1, 0 };
    opsA.v[8] = { (float*)p_stf, wtf + OFF_WB1, bb1, (float*)p_b1, 512, 64, 0, 0, 0, 0 };
    opsA.v[9] = { (float*)p_stf, wtf + OFF_WV1, bv1, (float*)p_v1, 512, 64, 0, 1, 0, 0 };
    packed_gemm<<<dim3(10, 128), 256, G_SMEM_BYTES>>>(opsA);

    // 5) second hypernet stage (one packed launch: w1 x8, wf)
    GOps opsB = {};
    for (int i = 0; i < 8; i++)
        opsB.v[i] = { (float*)p_h1, wtf + OFF_WH1B, bh1b, (float*)p_w1, 256, 512, i * 64, 2, 0, 0 };
    opsB.v[8]   = { (float*)p_hf, wtf + OFF_WHFB, bhfb, (float*)p_wf, 256, 64, 0, 2, 0, 0 };
    packed_gemm<<<dim3(9, 128), 256, G_SMEM_BYTES>>>(opsB);

    // 6) final mix -> y
    final_kernel<<<2048, 256>>>(Wv2, bv2, out);
}

// round 7
// speedup vs baseline: 2.6595x; 1.0378x over previous
#include <cuda_runtime.h>
#include <math.h>
#include <cstdint>

#define NTOT 16384
#define AS_F 4608          // 128*36 floats per stage
#define BS_F 2304          // 64*36 floats per stage

// ---------------- scratch (device globals; no allocation allowed) ----------
__device__ __align__(16) float g_x[131072 * 64];    // encoder out (tf32-rounded)
__device__ __align__(16) float g_stf[NTOT * 512];   // tf32-rounded states
__device__ __align__(16) float g_wtf[503808];       // tf32-rounded weights pool
__device__ __align__(16) float g_aq[NTOT * 8];
__device__ __align__(16) float g_h1[NTOT * 256];
__device__ __align__(16) float g_hf[NTOT * 256];
__device__ __align__(16) float g_w1[NTOT * 512];
__device__ __align__(16) float g_wf[NTOT * 64];
__device__ __align__(16) float g_b1[NTOT * 64];
__device__ __align__(16) float g_v1[NTOT * 64];

// offsets (floats) in g_wtf
#define OFF_WOBS 0
#define OFF_WQKV 16384
#define OFF_WH1A 28672
#define OFF_WHFA 159744
#define OFF_WH1B 290816
#define OFF_WHFB 421888
#define OFF_WB1  438272
#define OFF_WV1  471040
#define WTF_TOTAL 503808

// ---------------- helpers ---------------------------------------------------
__device__ __forceinline__ uint32_t f2tf(float x) {   // RNA round to tf32
    uint32_t r;
    asm("cvt.rna.tf32.f32 %0, %1;" : "=r"(r) : "f"(x));
    return r;
}
__device__ __forceinline__ uint32_t smem_u32(const void* p) {
    uint32_t a;
    asm("{ .reg .u64 t; cvta.to.shared.u64 t, %1; cvt.u32.u64 %0, t; }" : "=r"(a) : "l"(p));
    return a;
}
__device__ __forceinline__ void cp16(uint32_t s, const void* g) {
    asm volatile("cp.async.cg.shared.global [%0], [%1], 16;" :: "r"(s), "l"(g));
}
#define CP_COMMIT asm volatile("cp.async.commit_group;" ::: "memory")
#define CP_WAIT(N) asm volatile("cp.async.wait_group %0;" :: "n"(N) : "memory")

__device__ __forceinline__ void mma_tf32(float* c, const uint32_t* a, const uint32_t* b) {
    asm volatile(
        "mma.sync.aligned.m16n8k8.row.col.f32.tf32.tf32.f32 "
        "{%0,%1,%2,%3}, {%4,%5,%6,%7}, {%8,%9}, {%0,%1,%2,%3};\n"
        : "+f"(c[0]), "+f"(c[1]), "+f"(c[2]), "+f"(c[3])
        : "r"(a[0]), "r"(a[1]), "r"(a[2]), "r"(a[3]), "r"(b[0]), "r"(b[1]));
}

// ---- compute one 128x64x32 chunk from natural [r][36] tiles ----------------
// k-slot permutation: logical k = 8t + 2*kk8 + half  (applied to A & B)
template <int CVTA>
__device__ __forceinline__ void compute_chunk(
    const float* __restrict__ Ab, const float* __restrict__ Bb,
    float acc[2][4][4], int wm, int wn, int g, int t)
{
    float a8[4][8], b8[4][8];
#pragma unroll
    for (int i = 0; i < 4; i++) {
        const float* pr = Ab + (wm * 32 + i * 8 + g) * 36 + t * 8;
        *(float4*)&a8[i][0] = *(const float4*)pr;
        *(float4*)&a8[i][4] = *(const float4*)(pr + 4);
    }
#pragma unroll
    for (int i = 0; i < 4; i++) {
        const float* pr = Bb + (wn * 32 + i * 8 + g) * 36 + t * 8;
        *(float4*)&b8[i][0] = *(const float4*)pr;
        *(float4*)&b8[i][4] = *(const float4*)(pr + 4);
    }
#pragma unroll
    for (int k8 = 0; k8 < 4; k8++) {
        uint32_t af[2][4], bf[4][2];
#pragma unroll
        for (int mi = 0; mi < 2; mi++) {
            if (CVTA) {
                af[mi][0] = f2tf(a8[2 * mi][2 * k8]);
                af[mi][1] = f2tf(a8[2 * mi + 1][2 * k8]);
                af[mi][2] = f2tf(a8[2 * mi][2 * k8 + 1]);
                af[mi][3] = f2tf(a8[2 * mi + 1][2 * k8 + 1]);
            } else {
                af[mi][0] = __float_as_uint(a8[2 * mi][2 * k8]);
                af[mi][1] = __float_as_uint(a8[2 * mi + 1][2 * k8]);
                af[mi][2] = __float_as_uint(a8[2 * mi][2 * k8 + 1]);
                af[mi][3] = __float_as_uint(a8[2 * mi + 1][2 * k8 + 1]);
            }
        }
#pragma unroll
        for (int ni = 0; ni < 4; ni++) {
            bf[ni][0] = __float_as_uint(b8[ni][2 * k8]);
            bf[ni][1] = __float_as_uint(b8[ni][2 * k8 + 1]);
        }
#pragma unroll
        for (int mi = 0; mi < 2; mi++)
#pragma unroll
            for (int ni = 0; ni < 4; ni++)
                mma_tf32(acc[mi][ni], af[mi], bf[ni]);
    }
}

__device__ __forceinline__ void issue_stage(
    const float* __restrict__ A, const float* __restrict__ B, int K,
    int row0, int col0, uint32_t as_u, uint32_t bs_u, int c, int buf, int tid)
{
    const float* Ab = A + (size_t)row0 * K + c * 32;
    const uint32_t ad = as_u + (uint32_t)buf * AS_F * 4;
#pragma unroll
    for (int i = 0; i < 4; i++) {
        int e = tid + i * 256, r = e >> 3, q = e & 7;
        cp16(ad + (uint32_t)(r * 36 + q * 4) * 4, Ab + (size_t)r * K + q * 4);
    }
    const float* Bb = B + (size_t)col0 * K + c * 32;
    const uint32_t bd = bs_u + (uint32_t)buf * BS_F * 4;
#pragma unroll
    for (int i = 0; i < 2; i++) {
        int e = tid + i * 256, r = e >> 3, q = e & 7;
        cp16(bd + (uint32_t)(r * 36 + q * 4) * 4, Bb + (size_t)r * K + q * 4);
    }
}

// 4-stage pipeline, ONE barrier per chunk.
// Safety: issue at iter c targets buf (c+3)&3 == (c-1)&3, last read in
// compute(c-1); the barrier at iter-c start orders all warps past compute(c-1).
// Tail: unconditional (possibly empty) commit keeps CP_WAIT(2) == "group c done".
// Requires nk >= 3 (true for all launches here: nk in {8,16}).
template <int CVTA>
__device__ __forceinline__ void gemm_main(
    const float* __restrict__ A, const float* __restrict__ B, int K,
    int row0, int col0, float* Asf, float* Bsf,
    float acc[2][4][4], int tid, int wm, int wn, int g, int t)
{
    const uint32_t as_u = smem_u32(Asf), bs_u = smem_u32(Bsf);
    const int nk = K >> 5;
    issue_stage(A, B, K, row0, col0, as_u, bs_u, 0, 0, tid); CP_COMMIT;
    issue_stage(A, B, K, row0, col0, as_u, bs_u, 1, 1, tid); CP_COMMIT;
    issue_stage(A, B, K, row0, col0, as_u, bs_u, 2, 2, tid); CP_COMMIT;
    for (int c = 0; c < nk; c++) {
        CP_WAIT(2);
        __syncthreads();
        compute_chunk<CVTA>(Asf + (c & 3) * AS_F, Bsf + (c & 3) * BS_F, acc, wm, wn, g, t);
        if (c + 3 < nk)
            issue_stage(A, B, K, row0, col0, as_u, bs_u, c + 3, (c + 3) & 3, tid);
        CP_COMMIT;
    }
}

// ---------------- merged pre-conversion kernel ------------------------------
struct WSeg { const float* src; int off; int cnt; };
struct WSegs { WSeg v[8]; };
#define CVT_STATE_BLOCKS 8192
#define CVT_W_BLOCKS 492            // WTF_TOTAL / 1024

__global__ void __launch_bounds__(256) cvt_all_kernel(
    const float* __restrict__ s, float* __restrict__ d,
    WSegs segs, float* __restrict__ wdst)
{
    int b = blockIdx.x;
    if (b < CVT_STATE_BLOCKS) {
        size_t i = (size_t)(b * 256 + threadIdx.x) * 4;
        float4 v = *(const float4*)(s + i);
        uint4 u = { f2tf(v.x), f2tf(v.y), f2tf(v.z), f2tf(v.w) };
        *(uint4*)(d + i) = u;
    } else {
        int i4 = ((b - CVT_STATE_BLOCKS) * 256 + threadIdx.x) * 4;
#pragma unroll
        for (int k = 0; k < 8; k++) {
            int off = segs.v[k].off, cnt = segs.v[k].cnt;
            if (i4 >= off && i4 < off + cnt) {
                float4 v = *(const float4*)(segs.v[k].src + (i4 - off));
                uint4 u = { f2tf(v.x), f2tf(v.y), f2tf(v.z), f2tf(v.w) };
                *(uint4*)(wdst + i4) = u;
            }
        }
    }
}

// ---------------- encoder GEMM (obs raw -> x, tf32-rounded out) -------------
#define ENC_SMEM_BYTES ((4 * (AS_F + BS_F) + 192) * 4)

__global__ void __launch_bounds__(256, 2) enc_gemm(
    const float* __restrict__ obs, const float* __restrict__ Wobs_tf,
    const float* __restrict__ b_obs, float* __restrict__ Cx,
    const int* __restrict__ actions, const float* __restrict__ qvals,
    const float* __restrict__ W_act, const float* __restrict__ W_q,
    const float* __restrict__ b_act, const float* __restrict__ b_q)
{
    extern __shared__ float dsm[];
    float* Asf = dsm;
    float* Bsf = dsm + 4 * AS_F;
    float* bias_sh = dsm + 4 * (AS_F + BS_F);
    float* cvec_sh = bias_sh + 64;
    float* wq_sh   = cvec_sh + 64;

    const int tid = threadIdx.x;
    const int wid = tid >> 5, lane = tid & 31;
    const int wm = wid >> 1, wn = wid & 1;
    const int g = lane >> 2, t = lane & 3;
    const int row0 = blockIdx.y * 128;

    if (tid < 64) {
        bias_sh[tid] = b_obs[tid];
        cvec_sh[tid] = b_act[tid] + b_q[tid];
        wq_sh[tid] = W_q[tid];
    }

    float acc[2][4][4];
#pragma unroll
    for (int mi = 0; mi < 2; mi++)
#pragma unroll
        for (int ni = 0; ni < 4; ni++)
#pragma unroll
            for (int j = 0; j < 4; j++) acc[mi][ni][j] = 0.f;

    gemm_main<1>(obs, Wobs_tf, 256, row0, 0, Asf, Bsf, acc, tid, wm, wn, g, t);

#pragma unroll
    for (int mi = 0; mi < 2; mi++)
#pragma unroll
        for (int half = 0; half < 2; half++) {
            const int row = row0 + wm * 32 + mi * 16 + half * 8 + g;
            const int act = actions[row];
            const float qv = qvals[row];
            float* dst = Cx + (size_t)row * 64;
#pragma unroll
            for (int ni = 0; ni < 4; ni++) {
                const int lc = wn * 32 + ni * 8 + t * 2;
                float v0 = acc[mi][ni][half * 2 + 0] + bias_sh[lc]
                         + cvec_sh[lc] + __ldg(&W_act[lc * 32 + act]) + qv * wq_sh[lc];
                float v1 = acc[mi][ni][half * 2 + 1] + bias_sh[lc + 1]
                         + cvec_sh[lc + 1] + __ldg(&W_act[(lc + 1) * 32 + act]) + qv * wq_sh[lc + 1];
                float2 o = { __uint_as_float(f2tf(v0)), __uint_as_float(f2tf(v1)) };
                *(float2*)(dst + lc) = o;
            }
        }
}

// ---------------- packed GEMM (multiple ops per launch) ---------------------
struct GOp {
    const float* A; const float* B; const float* bias; float* C;
    int K; int Nout; int col0; int epi; int round; int pad;
};
struct GOps { GOp v[10]; };
#define G_SMEM_BYTES ((4 * (AS_F + BS_F) + 64) * 4)

__global__ void __launch_bounds__(256, 2) packed_gemm(GOps ops)
{
    extern __shared__ float dsm[];
    float* Asf = dsm;
    float* Bsf = dsm + 4 * AS_F;
    float* bias_sh = dsm + 4 * (AS_F + BS_F);

    const GOp op = ops.v[blockIdx.x];
    const int tid = threadIdx.x;
    const int wid = tid >> 5, lane = tid & 31;
    const int wm = wid >> 1, wn = wid & 1;
    const int g = lane >> 2, t = lane & 3;
    const int row0 = blockIdx.y * 128;
    const int col0 = op.col0;

    if (tid < 64) bias_sh[tid] = op.bias[col0 + tid];

    float acc[2][4][4];
#pragma unroll
    for (int mi = 0; mi < 2; mi++)
#pragma unroll
        for (int ni = 0; ni < 4; ni++)
#pragma unroll
            for (int j = 0; j < 4; j++) acc[mi][ni][j] = 0.f;

    gemm_main<0>(op.A, op.B, op.K, row0, col0, Asf, Bsf, acc, tid, wm, wn, g, t);

    const int epi = op.epi, rnd = op.round, Nout = op.Nout;
#pragma unroll
    for (int mi = 0; mi < 2; mi++)
#pragma unroll
        for (int half = 0; half < 2; half++) {
            const int row = row0 + wm * 32 + mi * 16 + half * 8 + g;
            float* dst = op.C + (size_t)row * Nout + col0;
#pragma unroll
            for (int ni = 0; ni < 4; ni++) {
                const int lc = wn * 32 + ni * 8 + t * 2;
                float v0 = acc[mi][ni][half * 2 + 0] + bias_sh[lc];
                float v1 = acc[mi][ni][half * 2 + 1] + bias_sh[lc + 1];
                if (epi == 1) { v0 = fmaxf(v0, 0.f); v1 = fmaxf(v1, 0.f); }
                else if (epi == 2) { v0 = fabsf(v0); v1 = fabsf(v1); }
                if (rnd) { v0 = __uint_as_float(f2tf(v0)); v1 = __uint_as_float(f2tf(v1)); }
                float2 o = { v0, v1 };
                *(float2*)(dst + lc) = o;
            }
        }
}

// ---------------- fused qkv GEMM + attention (+ inline wcomb) ---------------
#define QA_XS_F (2 * 128 * 36)
#define QA_WS_F (2 * 192 * 36)
#define QA_QS_F (128 * 196)
#define QA_SMEM_BYTES ((QA_XS_F + QA_WS_F + QA_QS_F + 192 + 65) * 4)

__global__ void __launch_bounds__(256) qkv_attn_kernel(
    const float* __restrict__ Wqkv_tf, const float* __restrict__ bqkv,
    const float* __restrict__ Wa2q, const float* __restrict__ ba2q,
    const float* __restrict__ Wo, const float* __restrict__ bo)
{
    extern __shared__ float sm[];
    float* xs = sm;                        // [2][128][36]
    float* ws = xs + QA_XS_F;              // [2][192][36]
    float* qs = ws + QA_WS_F;              // [128][196]
    float* bq = qs + QA_QS_F;              // 192
    float* wc = bq + 192;                  // 65

    const int tid = threadIdx.x;
    const int wid = tid >> 5, lane = tid & 31;
    const int wm = wid >> 1, wn = wid & 1;
    const int g = lane >> 2, t = lane & 3;
    const int row0 = blockIdx.x * 128;

    const uint32_t xs_u = smem_u32(xs);
    const uint32_t ws_u = smem_u32(ws);
#pragma unroll
    for (int i = 0; i < 8; i++) {          // x tile: 2048 float4
        int e = tid + i * 256;
        int r = e >> 4, q = e & 15;
        cp16(xs_u + (uint32_t)((q >> 3) * (128 * 36) + r * 36 + (q & 7) * 4) * 4,
             g_x + (size_t)(row0 + r) * 64 + q * 4);
    }
#pragma unroll
    for (int i = 0; i < 12; i++) {         // Wqkv: 3072 float4
        int e = tid + i * 256;
        int n = e >> 4, q = e & 15;
        cp16(ws_u + (uint32_t)((q >> 3) * (192 * 36) + n * 36 + (q & 7) * 4) * 4,
             Wqkv_tf + (size_t)n * 64 + q * 4);
    }
    if (tid < 192) bq[tid] = bqkv[tid];
    // inline wcomb = Wa2q @ Wo (hidden under cp.async wait)
    if (tid < 64) {
        float s = 0.f;
#pragma unroll 8
        for (int c = 0; c < 64; c++) s += Wa2q[c] * Wo[c * 64 + tid];
        wc[tid] = s;
    }
    if (wid == 6) {                        // bcomb = Wa2q.bo + ba2q
        float v = Wa2q[lane] * bo[lane] + Wa2q[lane + 32] * bo[lane + 32];
#pragma unroll
        for (int off = 16; off > 0; off >>= 1) v += __shfl_xor_sync(0xffffffffu, v, off);
        if (lane == 0) wc[64] = v + ba2q[0];
    }
    CP_COMMIT; CP_WAIT(0);
    __syncthreads();

    // ---- phase B: qkv = x @ Wqkv^T (3 col blocks of 64) ----
#pragma unroll 1
    for (int cb = 0; cb < 3; cb++) {
        float acc[2][4][4];
#pragma unroll
        for (int mi = 0; mi < 2; mi++)
#pragma unroll
            for (int ni = 0; ni < 4; ni++)
#pragma unroll
                for (int j = 0; j < 4; j++) acc[mi][ni][j] = 0.f;

#pragma unroll
        for (int c = 0; c < 2; c++)
            compute_chunk<0>(xs + c * (128 * 36),
                             ws + c * (192 * 36) + (cb * 64) * 36,
                             acc, wm, wn, g, t);

#pragma unroll
        for (int mi = 0; mi < 2; mi++)
#pragma unroll
            for (int half = 0; half < 2; half++) {
                const int row = wm * 32 + mi * 16 + half * 8 + g;
#pragma unroll
                for (int ni = 0; ni < 4; ni++) {
                    const int lc = wn * 32 + ni * 8 + t * 2;
                    qs[row * 196 + cb * 64 + lc]     = acc[mi][ni][half * 2 + 0] + bq[cb * 64 + lc];
                    qs[row * 196 + cb * 64 + lc + 1] = acc[mi][ni][half * 2 + 1] + bq[cb * 64 + lc + 1];
                }
            }
    }
    __syncthreads();

    // ---- phase C: attention per sample (2 samples per warp) ----
    const int h = lane >> 3, a = lane & 7;
#pragma unroll
    for (int s2 = 0; s2 < 2; s2++) {
        const int s = wid * 2 + s2;
        const float* base = qs + s * 8 * 196;

        float q[16];
#pragma unroll
        for (int d = 0; d < 16; d++) q[d] = base[a * 196 + h * 16 + d];
        float sc[8], m = -1e30f;
#pragma unroll
        for (int b = 0; b < 8; b++) {
            float acc = 0.f;
#pragma unroll
            for (int d = 0; d < 16; d++) acc += q[d] * base[b * 196 + 64 + h * 16 + d];
            sc[b] = acc * 0.25f;          // 1/sqrt(16)
            m = fmaxf(m, sc[b]);
        }
        float sum = 0.f;
#pragma unroll
        for (int b = 0; b < 8; b++) { sc[b] = __expf(sc[b] - m); sum += sc[b]; }
        float inv = 1.f / sum;
        float o[16];
#pragma unroll
        for (int d = 0; d < 16; d++) o[d] = 0.f;
#pragma unroll
        for (int b = 0; b < 8; b++) {
            float p = sc[b] * inv;
#pragma unroll
            for (int d = 0; d < 16; d++) o[d] += p * base[b * 196 + 128 + h * 16 + d];
        }
        float part = 0.f;
#pragma unroll
        for (int d = 0; d < 16; d++) part += o[d] * wc[h * 16 + d];
        part += __shfl_xor_sync(0xffffffffu, part, 8);
        part += __shfl_xor_sync(0xffffffffu, part, 16);
        if (h == 0) {
            const int n = blockIdx.x * 16 + s;
            g_aq[n * 8 + a] = part + wc[64];
        }
    }
}

// ---------------- final mixing: elu(aq @ w1 + b1) . w_f + v ----------------
__global__ void __launch_bounds__(256) final_kernel(
    const float* __restrict__ Wv2, const float* __restrict__ bv2,
    float* __restrict__ out)
{
    const int warp = threadIdx.x >> 5, lane = threadIdx.x & 31;
    const int n = blockIdx.x * 8 + warp;
    if (n >= NTOT) return;

    float aqv[8];
#pragma unroll
    for (int a = 0; a < 8; a++) aqv[a] = g_aq[n * 8 + a];

    float tot = 0.f;
#pragma unroll
    for (int jj = 0; jj < 2; jj++) {
        int e = jj * 32 + lane;
        float hsum = g_b1[n * 64 + e];
#pragma unroll
        for (int a = 0; a < 8; a++) hsum += aqv[a] * g_w1[(size_t)n * 512 + a * 64 + e];
        float hid = hsum > 0.f ? hsum : expm1f(hsum);
        tot += hid * g_wf[n * 64 + e] + g_v1[n * 64 + e] * Wv2[e];
    }
#pragma unroll
    for (int off = 16; off > 0; off >>= 1) tot += __shfl_xor_sync(0xffffffffu, tot, off);
    if (lane == 0) out[n] = tot + bv2[0];
}

// ---------------- launch ----------------------------------------------------
extern "C" void kernel_launch(void* const* d_in, const int* in_sizes, int n_in,
                              void* d_out, int out_size)
{
    const float* agent_qs = (const float*)d_in[0];
    const float* states   = (const float*)d_in[1];
    const float* obs      = (const float*)d_in[2];
    const int*   actions  = (const int*)d_in[3];
    const float* W_obs = (const float*)d_in[4];  const float* b_obs = (const float*)d_in[5];
    const float* W_act = (const float*)d_in[6];  const float* b_act = (const float*)d_in[7];
    const float* W_q   = (const float*)d_in[8];  const float* b_q   = (const float*)d_in[9];
    const float* Wqkv  = (const float*)d_in[10]; const float* bqkv  = (const float*)d_in[11];
    const float* Wo    = (const float*)d_in[12]; const float* bo    = (const float*)d_in[13];
    const float* Wa2q  = (const float*)d_in[14]; const float* ba2q  = (const float*)d_in[15];
    const float* Wh1a  = (const float*)d_in[16]; const float* bh1a  = (const float*)d_in[17];
    const float* Wh1b  = (const float*)d_in[18]; const float* bh1b  = (const float*)d_in[19];
    const float* Whfa  = (const float*)d_in[20]; const float* bhfa  = (const float*)d_in[21];
    const float* Whfb  = (const float*)d_in[22]; const float* bhfb  = (const float*)d_in[23];
    const float* Wb1   = (const float*)d_in[24]; const float* bb1   = (const float*)d_in[25];
    const float* Wv1   = (const float*)d_in[26]; const float* bv1   = (const float*)d_in[27];
    const float* Wv2   = (const float*)d_in[28]; const float* bv2   = (const float*)d_in[29];
    float* out = (float*)d_out;

    void *p_x, *p_stf, *p_wtf, *p_h1, *p_hf, *p_w1, *p_wf, *p_b1, *p_v1;
    cudaGetSymbolAddress(&p_x,   g_x);
    cudaGetSymbolAddress(&p_stf, g_stf);
    cudaGetSymbolAddress(&p_wtf, g_wtf);
    cudaGetSymbolAddress(&p_h1,  g_h1);
    cudaGetSymbolAddress(&p_hf,  g_hf);
    cudaGetSymbolAddress(&p_w1,  g_w1);
    cudaGetSymbolAddress(&p_wf,  g_wf);
    cudaGetSymbolAddress(&p_b1,  g_b1);
    cudaGetSymbolAddress(&p_v1,  g_v1);
    float* wtf = (float*)p_wtf;

    cudaFuncSetAttribute(enc_gemm,        cudaFuncAttributeMaxDynamicSharedMemorySize, ENC_SMEM_BYTES);
    cudaFuncSetAttribute(packed_gemm,     cudaFuncAttributeMaxDynamicSharedMemorySize, G_SMEM_BYTES);
    cudaFuncSetAttribute(qkv_attn_kernel, cudaFuncAttributeMaxDynamicSharedMemorySize, QA_SMEM_BYTES);

    // 0) pre-convert states + weights (one launch)
    WSegs segs;
    segs.v[0] = { W_obs, OFF_WOBS, 16384 };
    segs.v[1] = { Wqkv,  OFF_WQKV, 12288 };
    segs.v[2] = { Wh1a,  OFF_WH1A, 131072 };
    segs.v[3] = { Whfa,  OFF_WHFA, 131072 };
    segs.v[4] = { Wh1b,  OFF_WH1B, 131072 };
    segs.v[5] = { Whfb,  OFF_WHFB, 16384 };
    segs.v[6] = { Wb1,   OFF_WB1,  32768 };
    segs.v[7] = { Wv1,   OFF_WV1,  32768 };
    cvt_all_kernel<<<CVT_STATE_BLOCKS + CVT_W_BLOCKS, 256>>>(states, (float*)p_stf, segs, wtf);

    // 1) encoder -> g_x (tf32-rounded)
    enc_gemm<<<dim3(1, 1024), 256, ENC_SMEM_BYTES>>>(
        obs, wtf + OFF_WOBS, b_obs, (float*)p_x,
        actions, agent_qs, W_act, W_q, b_act, b_q);

    // 2) fused qkv + attention (wcomb inline) -> attended_qs
    qkv_attn_kernel<<<1024, 256, QA_SMEM_BYTES>>>(wtf + OFF_WQKV, bqkv, Wa2q, ba2q, Wo, bo);

    // 3) hypernets on states (one packed launch: h1 x4, hf x4, b1, v1)
    GOps opsA = {};
    for (int i = 0; i < 4; i++)
        opsA.v[i]     = { (float*)p_stf, wtf + OFF_WH1A, bh1a, (float*)p_h1, 512, 256, i * 64, 1, 1, 0 };
    for (int i = 0; i < 4; i++)
        opsA.v[4 + i] = { (float*)p_stf, wtf + OFF_WHFA, bhfa, (float*)p_hf, 512, 256, i * 64, 1, 1, 0 };
    opsA.v[8] = { (float*)p_stf, wtf + OFF_WB1, bb1, (float*)p_b1, 512, 64, 0, 0, 0, 0 };
    opsA.v[9] = { (float*)p_stf, wtf + OFF_WV1, bv1, (float*)p_v1, 512, 64, 0, 1, 0, 0 };
    packed_gemm<<<dim3(10, 128), 256, G_SMEM_BYTES>>>(opsA);

    // 4) second hypernet stage (one packed launch: w1 x8, wf)
    GOps opsB = {};
    for (int i = 0; i < 8; i++)
        opsB.v[i] = { (float*)p_h1, wtf + OFF_WH1B, bh1b, (float*)p_w1, 256, 512, i * 64, 2, 0, 0 };
    opsB.v[8]   = { (float*)p_hf, wtf + OFF_WHFB, bhfb, (float*)p_wf, 256, 64, 0, 2, 0, 0 };
    packed_gemm<<<dim3(9, 128), 256, G_SMEM_BYTES>>>(opsB);

    // 5) final mix -> y
    final_kernel<<<2048, 256>>>(Wv2, bv2, out);
}